// round 13
// baseline (speedup 1.0000x reference)
#include <cuda_runtime.h>
#include <cuda_bf16.h>
#include <math.h>
#include <stdint.h>

// Problem constants
#define BATCH   16
#define SEQ     1024
#define CH      1024
#define HEADS   16
#define DH      64
#define TOKENS  (BATCH*SEQ)      // 16384
#define LN_EPS  1e-6f
#define QSCALE  0.125f           // Dh^-0.5

// Scratch (device globals: allocation-free per harness rules)
__device__ uint16_t g_yh[TOKENS*CH]; __device__ uint16_t g_yl[TOKENS*CH];
__device__ uint16_t g_wh[4*CH*CH];   __device__ uint16_t g_wl[4*CH*CH];
// per-head planes [B,H,N,DH]
__device__ uint16_t g_qh[TOKENS*CH]; __device__ uint16_t g_ql[TOKENS*CH];
__device__ uint16_t g_kh[TOKENS*CH]; __device__ uint16_t g_kl[TOKENS*CH];
__device__ uint16_t g_vh[TOKENS*CH]; __device__ uint16_t g_vl[TOKENS*CH];
// attention output planes in [token][CH] layout
__device__ uint16_t g_aoh[TOKENS*CH]; __device__ uint16_t g_aol[TOKENS*CH];

// ---------------------------------------------------------------------------
// helpers
// ---------------------------------------------------------------------------
__device__ __forceinline__ uint32_t smem_u32(const void* p) {
    return (uint32_t)__cvta_generic_to_shared(p);
}
__device__ __forceinline__ void ldsm_x4(uint32_t& r0, uint32_t& r1,
                                        uint32_t& r2, uint32_t& r3, uint32_t addr) {
    asm volatile("ldmatrix.sync.aligned.m8n8.x4.shared.b16 {%0,%1,%2,%3},[%4];"
                 : "=r"(r0), "=r"(r1), "=r"(r2), "=r"(r3) : "r"(addr));
}
__device__ __forceinline__ void ldsm_x4_t(uint32_t& r0, uint32_t& r1,
                                          uint32_t& r2, uint32_t& r3, uint32_t addr) {
    asm volatile("ldmatrix.sync.aligned.m8n8.x4.trans.shared.b16 {%0,%1,%2,%3},[%4];"
                 : "=r"(r0), "=r"(r1), "=r"(r2), "=r"(r3) : "r"(addr));
}
__device__ __forceinline__ void mma_bf16(float* c,
                                         uint32_t a0, uint32_t a1, uint32_t a2, uint32_t a3,
                                         uint32_t b0, uint32_t b1) {
    asm volatile("mma.sync.aligned.m16n8k16.row.col.f32.bf16.bf16.f32 "
                 "{%0,%1,%2,%3},{%4,%5,%6,%7},{%8,%9},{%0,%1,%2,%3};"
                 : "+f"(c[0]), "+f"(c[1]), "+f"(c[2]), "+f"(c[3])
                 : "r"(a0), "r"(a1), "r"(a2), "r"(a3), "r"(b0), "r"(b1));
}
__device__ __forceinline__ uint32_t pack_bf2(float lo, float hi) {
    __nv_bfloat162 t = __floats2bfloat162_rn(lo, hi);
    return *(uint32_t*)&t;
}
__device__ __forceinline__ void split2(float a, float b, uint32_t& hi, uint32_t& lo) {
    __nv_bfloat16 ha = __float2bfloat16(a);
    __nv_bfloat16 hb = __float2bfloat16(b);
    hi = (uint32_t)__bfloat16_as_ushort(ha) | ((uint32_t)__bfloat16_as_ushort(hb) << 16);
    lo = pack_bf2(a - __bfloat162float(ha), b - __bfloat162float(hb));
}
__device__ __forceinline__ void split_pack(float4 f, uint32_t& h01, uint32_t& h23,
                                           uint32_t& l01, uint32_t& l23) {
    split2(f.x, f.y, h01, l01);
    split2(f.z, f.w, h23, l23);
}

#define CP16(dst, src) asm volatile("cp.async.cg.shared.global [%0],[%1],16;" :: "r"(dst), "l"(src))
#define CPCOMMIT()     asm volatile("cp.async.commit_group;")
#define CPWAIT1()      asm volatile("cp.async.wait_group 1;")
#define CPWAIT0()      asm volatile("cp.async.wait_group 0;")

// ---------------------------------------------------------------------------
// Kernel 1: LayerNorm over C=1024 + direct split to bf16 hi/lo planes.
// ---------------------------------------------------------------------------
__global__ __launch_bounds__(256) void ln_split_rows(const float* __restrict__ x,
                                                     uint16_t* __restrict__ yh,
                                                     uint16_t* __restrict__ yl)
{
    int row = blockIdx.x;
    int t = threadIdx.x;
    const float4* xr = (const float4*)(x + (size_t)row * CH);

    float4 v = xr[t];
    float s  = v.x + v.y + v.z + v.w;
    float ss = v.x*v.x + v.y*v.y + v.z*v.z + v.w*v.w;

    #pragma unroll
    for (int o = 16; o; o >>= 1) {
        s  += __shfl_xor_sync(0xFFFFFFFFu, s,  o);
        ss += __shfl_xor_sync(0xFFFFFFFFu, ss, o);
    }
    __shared__ float sh[16];
    int w = t >> 5, l = t & 31;
    if (l == 0) { sh[w] = s; sh[8 + w] = ss; }
    __syncthreads();
    float S = 0.f, SS = 0.f;
    #pragma unroll
    for (int i = 0; i < 8; i++) { S += sh[i]; SS += sh[8 + i]; }

    float mean = S * (1.0f / CH);
    float var  = SS * (1.0f / CH) - mean * mean;
    float inv  = rsqrtf(var + LN_EPS);

    v.x = (v.x - mean) * inv;
    v.y = (v.y - mean) * inv;
    v.z = (v.z - mean) * inv;
    v.w = (v.w - mean) * inv;

    uint32_t h01, h23, l01, l23;
    split_pack(v, h01, h23, l01, l23);
    size_t off = (size_t)row * CH + t * 4;
    *(uint2*)(yh + off) = make_uint2(h01, h23);
    *(uint2*)(yl + off) = make_uint2(l01, l23);
}

// ---------------------------------------------------------------------------
// Kernel 1b: split weights (4 matrices) to bf16 hi/lo planes.
// ---------------------------------------------------------------------------
__global__ __launch_bounds__(256) void w_split(const float* __restrict__ W0,
                                               const float* __restrict__ W1,
                                               const float* __restrict__ W2,
                                               const float* __restrict__ W3,
                                               uint16_t* __restrict__ wh,
                                               uint16_t* __restrict__ wl)
{
    int z = blockIdx.y;
    const float* W = (z == 0) ? W0 : (z == 1) ? W1 : (z == 2) ? W2 : W3;
    size_t base = (size_t)z * CH * CH;
    size_t off  = ((size_t)blockIdx.x * 256 + threadIdx.x) * 4;

    float4 f = *(const float4*)(W + off);
    uint32_t h01, h23, l01, l23;
    split_pack(f, h01, h23, l01, l23);
    *(uint2*)(wh + base + off) = make_uint2(h01, h23);
    *(uint2*)(wl + base + off) = make_uint2(l01, l23);
}

// ---------------------------------------------------------------------------
// Kernel 2: pure-bf16 tensor-core GEMM (NT), cp.async double-buffered.
// 2-stage, 128x128x32, warp tile 64x32. A-fragments loaded per-mt (live set
// ~110 regs) so the 128-reg cap from __launch_bounds__(256,2) does not spill
// -> true 2 CTAs/SM. mma order per accumulator unchanged (bit-identical).
// QKV3 epilogue: smem-staged fused head-LN + split. !QKV3: fp32 + bias.
// ---------------------------------------------------------------------------
#define BK    32
#define PADK  40
#define PLANE (128*PADK)   // bf16 elements per smem plane
#define EPAD  132          // epilogue staging row stride (floats, mult of 4)

template<bool QKV3>
__global__ __launch_bounds__(256, 2) void gemm_async(const uint16_t* __restrict__ Ah,
                                                     const uint16_t* __restrict__ Al,
                                                     const uint16_t* __restrict__ Bh_,
                                                     const uint16_t* __restrict__ Bl_,
                                                     const float* __restrict__ bias,
                                                     float* __restrict__ C,
                                                     uint16_t* __restrict__ pqh,
                                                     uint16_t* __restrict__ pql,
                                                     uint16_t* __restrict__ pkh,
                                                     uint16_t* __restrict__ pkl,
                                                     uint16_t* __restrict__ pvh,
                                                     uint16_t* __restrict__ pvl)
{
    extern __shared__ __align__(16) uint16_t smg[];

    int z = QKV3 ? blockIdx.z : 3;
    const uint16_t* Bh = Bh_;
    const uint16_t* Bl = Bl_;
    if (QKV3) {
        size_t zo = (size_t)z * CH * CH;
        Bh += zo; Bl += zo;
    }

    int t    = threadIdx.x;
    int lane = t & 31;
    int warp = t >> 5;
    int wm64 = (warp >> 2) * 64;
    int wn32 = (warp & 3) * 32;
    int bm = blockIdx.y * 128;
    int bn = blockIdx.x * 128;

    const uint16_t* Agh = Ah + (size_t)bm * CH;
    const uint16_t* Agl = Al + (size_t)bm * CH;
    const uint16_t* Bgh = Bh + (size_t)bn * CH;
    const uint16_t* Bgl = Bl + (size_t)bn * CH;

    uint32_t smem_base = smem_u32(smg);

    float acc[4][4][4];
    #pragma unroll
    for (int i = 0; i < 4; i++)
        #pragma unroll
        for (int j = 0; j < 4; j++)
            #pragma unroll
            for (int c = 0; c < 4; c++) acc[i][j][c] = 0.f;

    // per-thread cp.async chunks: 2 per plane (512 chunks of 16B per plane)
    int c0r = t >> 2,          c0c = (t & 3) * 8;
    int c1r = (t + 256) >> 2,  c1c = ((t + 256) & 3) * 8;

    auto issue = [&](int stage, int k0) {
        uint32_t sb = smem_base + stage * (4 * PLANE * 2);
        uint32_t s0 = sb + (c0r * PADK + c0c) * 2;
        uint32_t s1 = sb + (c1r * PADK + c1c) * 2;
        CP16(s0 + 0*PLANE*2, Agh + (size_t)c0r * CH + k0 + c0c);
        CP16(s1 + 0*PLANE*2, Agh + (size_t)c1r * CH + k0 + c1c);
        CP16(s0 + 1*PLANE*2, Agl + (size_t)c0r * CH + k0 + c0c);
        CP16(s1 + 1*PLANE*2, Agl + (size_t)c1r * CH + k0 + c1c);
        CP16(s0 + 2*PLANE*2, Bgh + (size_t)c0r * CH + k0 + c0c);
        CP16(s1 + 2*PLANE*2, Bgh + (size_t)c1r * CH + k0 + c1c);
        CP16(s0 + 3*PLANE*2, Bgl + (size_t)c0r * CH + k0 + c0c);
        CP16(s1 + 3*PLANE*2, Bgl + (size_t)c1r * CH + k0 + c1c);
        CPCOMMIT();
    };

    int a_r    = lane & 15;
    int a_koff = (lane >> 4) << 3;
    int b_n    = (lane & 7) + ((lane >> 4) << 3);
    int b_koff = ((lane >> 3) & 1) << 3;

    const int T = CH / BK;   // 32
    issue(0, 0);
    issue(1, BK);

    for (int i = 0; i < T; i++) {
        if (i + 1 < T) { CPWAIT1(); } else { CPWAIT0(); }
        __syncthreads();

        uint16_t* sAh = smg + (i & 1) * 4 * PLANE;
        uint16_t* sAl = sAh + PLANE;
        uint16_t* sBh = sAl + PLANE;
        uint16_t* sBl = sBh + PLANE;

        #pragma unroll
        for (int kc = 0; kc < 2; kc++) {
            int ko = kc * 16;
            uint32_t bh[4][2], bl[4][2];
            #pragma unroll
            for (int p = 0; p < 2; p++) {
                int off = (wn32 + p * 16 + b_n) * PADK + ko + b_koff;
                uint32_t r0, r1, r2, r3;
                ldsm_x4(r0, r1, r2, r3, smem_u32(&sBh[off]));
                bh[2*p][0] = r0; bh[2*p][1] = r1; bh[2*p+1][0] = r2; bh[2*p+1][1] = r3;
                ldsm_x4(r0, r1, r2, r3, smem_u32(&sBl[off]));
                bl[2*p][0] = r0; bl[2*p][1] = r1; bl[2*p+1][0] = r2; bl[2*p+1][1] = r3;
            }
            // A fragments loaded per-mt: live set = 8 A regs + 16 B regs
            #pragma unroll
            for (int mt = 0; mt < 4; mt++) {
                uint32_t a0,a1,a2,a3, x0,x1,x2,x3;
                int off = (wm64 + mt * 16 + a_r) * PADK + ko + a_koff;
                ldsm_x4(a0,a1,a2,a3, smem_u32(&sAh[off]));
                ldsm_x4(x0,x1,x2,x3, smem_u32(&sAl[off]));
                #pragma unroll
                for (int nt = 0; nt < 4; nt++) {
                    float* c = acc[mt][nt];
                    mma_bf16(c, a0,a1,a2,a3, bh[nt][0], bh[nt][1]);
                    mma_bf16(c, a0,a1,a2,a3, bl[nt][0], bl[nt][1]);
                    mma_bf16(c, x0,x1,x2,x3, bh[nt][0], bh[nt][1]);
                }
            }
        }
        __syncthreads();
        if (i + 2 < T) issue(i & 1, (i + 2) * BK);
    }

    int lane4 = lane >> 2;
    int lpair = (lane & 3) * 2;

    if (QKV3) {
        // ---- stage fp32 tile to smem (reuse pipeline buffer; 128x132 floats) ----
        float* st = (float*)smg;
        #pragma unroll
        for (int mt = 0; mt < 4; mt++) {
            int r0 = wm64 + mt * 16 + lane4;
            #pragma unroll
            for (int nt = 0; nt < 4; nt++) {
                int col = wn32 + nt * 8 + lpair;
                float* c = acc[mt][nt];
                *(float2*)&st[(size_t)r0 * EPAD + col]       = make_float2(c[0], c[1]);
                *(float2*)&st[(size_t)(r0 + 8) * EPAD + col] = make_float2(c[2], c[3]);
            }
        }
        __syncthreads();

        // ---- thread-per-(row, head): LN + split + coalesced plane write ----
        uint16_t* dh = (z == 0) ? pqh : (z == 1) ? pkh : pvh;
        uint16_t* dl = (z == 0) ? pql : (z == 1) ? pkl : pvl;
        float sc = (z == 0) ? QSCALE : 1.0f;

        int r   = t >> 1;                 // 0..127 tile row
        int hh  = t & 1;                  // which head half of the 128 cols
        const float* v = st + (size_t)r * EPAD + hh * 64;

        float mean = 0.f, inv = 1.f;
        if (z < 2) {
            float s = 0.f, ss = 0.f;
            #pragma unroll
            for (int j = 0; j < 16; j++) {
                float4 f = *(const float4*)(v + j * 4);
                s  += (f.x + f.y) + (f.z + f.w);
                ss += (f.x*f.x + f.y*f.y) + (f.z*f.z + f.w*f.w);
            }
            mean = s * (1.0f / DH);
            float var = ss * (1.0f / DH) - mean * mean;
            inv = rsqrtf(var + LN_EPS) * sc;
        }

        int row = bm + r;
        int bb  = row >> 10, n = row & 1023;
        int h   = blockIdx.x * 2 + hh;
        size_t base = (((size_t)(bb * HEADS + h)) * SEQ + n) * DH;
        #pragma unroll
        for (int j = 0; j < 16; j++) {
            float4 f = *(const float4*)(v + j * 4);
            f.x = (f.x - mean) * inv; f.y = (f.y - mean) * inv;
            f.z = (f.z - mean) * inv; f.w = (f.w - mean) * inv;
            uint32_t h01, h23, l01, l23;
            split_pack(f, h01, h23, l01, l23);
            *(uint2*)(dh + base + j * 4) = make_uint2(h01, h23);
            *(uint2*)(dl + base + j * 4) = make_uint2(l01, l23);
        }
    } else {
        // out-projection: fp32 + bias, direct
        #pragma unroll
        for (int mt = 0; mt < 4; mt++) {
            int row = bm + wm64 + mt * 16 + lane4;
            #pragma unroll
            for (int nt = 0; nt < 4; nt++) {
                int col = bn + wn32 + nt * 8 + lpair;
                float b0 = bias[col], b1 = bias[col + 1];
                float* c = acc[mt][nt];
                *(float2*)(C + (size_t)row * CH + col)       = make_float2(c[0] + b0, c[1] + b1);
                *(float2*)(C + (size_t)(row + 8) * CH + col) = make_float2(c[2] + b0, c[3] + b1);
            }
        }
    }
}

// ---------------------------------------------------------------------------
// Kernel 3: tensor-core flash attention (no max tracking: |s|<=8).
// Q fragments re-ldsm'd per ch (frees regs); __launch_bounds__(256, 2)
// -> 128 regs -> 2 CTAs/SM. 3-pass QK^T; 3-pass P*V; KV double-buffered.
// ---------------------------------------------------------------------------
#define SSTR    72
#define KV_B    (4*64*SSTR)        // bf16 elements per KV stage

__global__ __launch_bounds__(256, 2) void attn_tc(const uint16_t* __restrict__ qh,
                                                  const uint16_t* __restrict__ ql,
                                                  const uint16_t* __restrict__ kh,
                                                  const uint16_t* __restrict__ kl,
                                                  const uint16_t* __restrict__ vh,
                                                  const uint16_t* __restrict__ vl,
                                                  uint16_t* __restrict__ aoh,
                                                  uint16_t* __restrict__ aol)
{
    extern __shared__ __align__(16) uint16_t sm[];
    uint16_t* Qh = sm;                       // 128*SSTR
    uint16_t* Ql = Qh + 128 * SSTR;
    uint16_t* KV = Ql + 128 * SSTR;          // 2 stages of KV_B

    int bh = blockIdx.x;
    int qb = blockIdx.y * 128;
    int t = threadIdx.x, lane = t & 31, warp = t >> 5;
    size_t plane = (size_t)bh * SEQ * DH;

    int k0r = t >> 3,         k0c = (t & 7) * 8;
    int k1r = (t + 256) >> 3, k1c = ((t + 256) & 7) * 8;
    uint32_t kv_base = smem_u32(KV);

    auto issue_kv = [&](int stage, int kt) {
        uint32_t sb = kv_base + stage * (KV_B * 2);
        uint32_t s0 = sb + (k0r * SSTR + k0c) * 2;
        uint32_t s1 = sb + (k1r * SSTR + k1c) * 2;
        size_t g0 = plane + (size_t)(kt + k0r) * DH + k0c;
        size_t g1 = plane + (size_t)(kt + k1r) * DH + k1c;
        const int PL = 64 * SSTR * 2;
        CP16(s0 + 0*PL, kh + g0);  CP16(s1 + 0*PL, kh + g1);
        CP16(s0 + 1*PL, kl + g0);  CP16(s1 + 1*PL, kl + g1);
        CP16(s0 + 2*PL, vh + g0);  CP16(s1 + 2*PL, vh + g1);
        CP16(s0 + 3*PL, vl + g0);  CP16(s1 + 3*PL, vl + g1);
        CPCOMMIT();
    };

    issue_kv(0, 0);
    issue_kv(1, 64);

    #pragma unroll
    for (int i = 0; i < 4; i++) {
        int f = t + i * 256;
        int row = f >> 3, c = (f & 7) * 8;
        size_t src = plane + (size_t)(qb + row) * DH + c;
        *(uint4*)&Qh[row * SSTR + c] = *(const uint4*)(qh + src);
        *(uint4*)&Ql[row * SSTR + c] = *(const uint4*)(ql + src);
    }
    __syncthreads();

    int a_r = lane & 15, a_ko = (lane >> 4) << 3;

    float oacc[8][4];
    #pragma unroll
    for (int i = 0; i < 8; i++)
        #pragma unroll
        for (int j = 0; j < 4; j++) oacc[i][j] = 0.f;
    float l0 = 0.f, l1 = 0.f;

    int b_n  = (lane & 7) + ((lane >> 4) << 3);
    int b_ko = ((lane >> 3) & 1) << 3;
    int v_r  = lane & 15;
    int v_co = (lane >> 4) * 8;

    const int T = SEQ / 64;
    for (int i = 0; i < T; i++) {
        if (i + 1 < T) { CPWAIT1(); } else { CPWAIT0(); }
        __syncthreads();

        uint16_t* Kh = KV + (i & 1) * KV_B;
        uint16_t* Kl = Kh + 64 * SSTR;
        uint16_t* Vh = Kl + 64 * SSTR;
        uint16_t* Vl = Vh + 64 * SSTR;

        float sacc[8][4];
        #pragma unroll
        for (int a = 0; a < 8; a++)
            #pragma unroll
            for (int c = 0; c < 4; c++) sacc[a][c] = 0.f;

        // ----- S = Q K^T (3-pass), ch-outer; Q fragments re-ldsm'd per ch -----
        #pragma unroll
        for (int ch = 0; ch < 4; ch++) {
            uint32_t q0,q1,q2,q3, e0,e1,e2,e3;
            int qoff = (warp * 16 + a_r) * SSTR + ch * 16 + a_ko;
            ldsm_x4(q0,q1,q2,q3, smem_u32(&Qh[qoff]));
            ldsm_x4(e0,e1,e2,e3, smem_u32(&Ql[qoff]));
            #pragma unroll
            for (int kp = 0; kp < 4; kp++) {
                int off = (kp * 16 + b_n) * SSTR + ch * 16 + b_ko;
                uint32_t h0,h1,h2,h3, f0,f1,f2,f3;
                ldsm_x4(h0,h1,h2,h3, smem_u32(&Kh[off]));
                ldsm_x4(f0,f1,f2,f3, smem_u32(&Kl[off]));
                float* c0 = sacc[2*kp];
                float* c1 = sacc[2*kp+1];
                mma_bf16(c0, q0,q1,q2,q3, h0,h1);
                mma_bf16(c1, q0,q1,q2,q3, h2,h3);
                mma_bf16(c0, q0,q1,q2,q3, f0,f1);
                mma_bf16(c1, q0,q1,q2,q3, f2,f3);
                mma_bf16(c0, e0,e1,e2,e3, h0,h1);
                mma_bf16(c1, e0,e1,e2,e3, h2,h3);
            }
        }

        // ----- exp + l accumulation -----
        #pragma unroll
        for (int nt = 0; nt < 8; nt++) {
            float p0 = __expf(sacc[nt][0]);
            float p1 = __expf(sacc[nt][1]);
            float p2 = __expf(sacc[nt][2]);
            float p3 = __expf(sacc[nt][3]);
            sacc[nt][0] = p0; sacc[nt][1] = p1;
            sacc[nt][2] = p2; sacc[nt][3] = p3;
            l0 += p0 + p1;
            l1 += p2 + p3;
        }

        // ----- O += P V (3-pass) -----
        #pragma unroll
        for (int j = 0; j < 4; j++) {
            uint32_t ph[4], pl[4];
            float* ca = sacc[2*j];
            float* cb = sacc[2*j+1];
            split2(ca[0], ca[1], ph[0], pl[0]);
            split2(ca[2], ca[3], ph[1], pl[1]);
            split2(cb[0], cb[1], ph[2], pl[2]);
            split2(cb[2], cb[3], ph[3], pl[3]);
            #pragma unroll
            for (int dp = 0; dp < 4; dp++) {
                int off = (j * 16 + v_r) * SSTR + dp * 16 + v_co;
                uint32_t b0,b1,b2,b3, f0,f1,f2,f3;
                ldsm_x4_t(b0,b1,b2,b3, smem_u32(&Vh[off]));
                ldsm_x4_t(f0,f1,f2,f3, smem_u32(&Vl[off]));
                float* o0 = oacc[2*dp];
                float* o1 = oacc[2*dp+1];
                mma_bf16(o0, ph[0],ph[1],ph[2],ph[3], b0,b1);
                mma_bf16(o0, ph[0],ph[1],ph[2],ph[3], f0,f1);
                mma_bf16(o0, pl[0],pl[1],pl[2],pl[3], b0,b1);
                mma_bf16(o1, ph[0],ph[1],ph[2],ph[3], b2,b3);
                mma_bf16(o1, ph[0],ph[1],ph[2],ph[3], f2,f3);
                mma_bf16(o1, pl[0],pl[1],pl[2],pl[3], b2,b3);
            }
        }

        __syncthreads();
        if (i + 2 < T) issue_kv(i & 1, (i + 2) * 64);
    }

    l0 += __shfl_xor_sync(0xFFFFFFFFu, l0, 1);
    l0 += __shfl_xor_sync(0xFFFFFFFFu, l0, 2);
    l1 += __shfl_xor_sync(0xFFFFFFFFu, l1, 1);
    l1 += __shfl_xor_sync(0xFFFFFFFFu, l1, 2);
    float rl0 = 1.0f / l0, rl1 = 1.0f / l1;

    int b = bh >> 4, h = bh & 15;
    int r0 = qb + warp * 16 + (lane >> 2);
    size_t base0 = ((size_t)(b * SEQ + r0)) * CH + h * DH + (lane & 3) * 2;
    size_t base1 = base0 + 8 * CH;
    #pragma unroll
    for (int nt = 0; nt < 8; nt++) {
        uint32_t hi, lo;
        split2(oacc[nt][0] * rl0, oacc[nt][1] * rl0, hi, lo);
        *(uint32_t*)(aoh + base0 + nt * 8) = hi;
        *(uint32_t*)(aol + base0 + nt * 8) = lo;
        split2(oacc[nt][2] * rl1, oacc[nt][3] * rl1, hi, lo);
        *(uint32_t*)(aoh + base1 + nt * 8) = hi;
        *(uint32_t*)(aol + base1 + nt * 8) = lo;
    }
}

// ---------------------------------------------------------------------------
// Launch
// ---------------------------------------------------------------------------
extern "C" void kernel_launch(void* const* d_in, const int* in_sizes, int n_in,
                              void* d_out, int out_size)
{
    const float* x  = (const float*)d_in[0];
    const float* Wq = (const float*)d_in[1];
    const float* Wk = (const float*)d_in[2];
    const float* Wv = (const float*)d_in[3];
    const float* Wp = (const float*)d_in[4];
    const float* bp = (const float*)d_in[5];
    float* out = (float*)d_out;

    uint16_t *p_yh, *p_yl, *p_wh, *p_wl;
    uint16_t *p_qh, *p_ql, *p_kh, *p_kl, *p_vh, *p_vl, *p_aoh, *p_aol;
    cudaGetSymbolAddress((void**)&p_yh, g_yh);
    cudaGetSymbolAddress((void**)&p_yl, g_yl);
    cudaGetSymbolAddress((void**)&p_wh, g_wh);
    cudaGetSymbolAddress((void**)&p_wl, g_wl);
    cudaGetSymbolAddress((void**)&p_qh, g_qh);
    cudaGetSymbolAddress((void**)&p_ql, g_ql);
    cudaGetSymbolAddress((void**)&p_kh, g_kh);
    cudaGetSymbolAddress((void**)&p_kl, g_kl);
    cudaGetSymbolAddress((void**)&p_vh, g_vh);
    cudaGetSymbolAddress((void**)&p_vl, g_vl);
    cudaGetSymbolAddress((void**)&p_aoh, g_aoh);
    cudaGetSymbolAddress((void**)&p_aol, g_aol);

    const int GEMM_SMEM = 2 * 4 * PLANE * 2;                   // 81920 B
    const int ATT_SMEM  = (2 * 128 * SSTR + 2 * KV_B) * 2;     // 110592 B
    static int configured = 0;
    if (!configured) {
        cudaFuncSetAttribute(gemm_async<true>,
                             cudaFuncAttributeMaxDynamicSharedMemorySize, GEMM_SMEM);
        cudaFuncSetAttribute(gemm_async<false>,
                             cudaFuncAttributeMaxDynamicSharedMemorySize, GEMM_SMEM);
        cudaFuncSetAttribute(attn_tc,
                             cudaFuncAttributeMaxDynamicSharedMemorySize, ATT_SMEM);
        configured = 1;
    }

    // 1. Pre-LN fused with bf16 split
    ln_split_rows<<<TOKENS, 256>>>(x, p_yh, p_yl);

    // 1b. Split weights
    w_split<<<dim3(CH * CH / 1024, 4), 256>>>(Wq, Wk, Wv, Wp, p_wh, p_wl);

    // 2. QKV projections with fused head-LN + split epilogue (smem-staged)
    dim3 gqkv(CH / 128, TOKENS / 128, 3);
    gemm_async<true><<<gqkv, 256, GEMM_SMEM>>>(p_yh, p_yl, p_wh, p_wl,
                                               nullptr, nullptr,
                                               p_qh, p_ql, p_kh, p_kl, p_vh, p_vl);

    // 3. Tensor-core flash attention (writes split planes)
    attn_tc<<<dim3(BATCH * HEADS, SEQ / 128), 256, ATT_SMEM>>>(p_qh, p_ql, p_kh, p_kl,
                                                               p_vh, p_vl, p_aoh, p_aol);

    // 4. Output projection + bias
    dim3 gout(CH / 128, TOKENS / 128, 1);
    gemm_async<false><<<gout, 256, GEMM_SMEM>>>(p_aoh, p_aol,
                                                p_wh + (size_t)3 * CH * CH,
                                                p_wl + (size_t)3 * CH * CH,
                                                bp, out,
                                                nullptr, nullptr, nullptr, nullptr,
                                                nullptr, nullptr);
}

// round 14
// speedup vs baseline: 1.0152x; 1.0152x over previous
#include <cuda_runtime.h>
#include <cuda_bf16.h>
#include <math.h>
#include <stdint.h>

// Problem constants
#define BATCH   16
#define SEQ     1024
#define CH      1024
#define HEADS   16
#define DH      64
#define TOKENS  (BATCH*SEQ)      // 16384
#define LN_EPS  1e-6f
#define QSCALE  0.125f           // Dh^-0.5

// Scratch (device globals: allocation-free per harness rules)
__device__ uint16_t g_yh[TOKENS*CH]; __device__ uint16_t g_yl[TOKENS*CH];
__device__ uint16_t g_wh[4*CH*CH];   __device__ uint16_t g_wl[4*CH*CH];
// per-head planes [B,H,N,DH]
__device__ uint16_t g_qh[TOKENS*CH]; __device__ uint16_t g_ql[TOKENS*CH];
__device__ uint16_t g_kh[TOKENS*CH]; __device__ uint16_t g_kl[TOKENS*CH];
__device__ uint16_t g_vh[TOKENS*CH]; __device__ uint16_t g_vl[TOKENS*CH];
// attention output planes in [token][CH] layout
__device__ uint16_t g_aoh[TOKENS*CH]; __device__ uint16_t g_aol[TOKENS*CH];

// ---------------------------------------------------------------------------
// helpers
// ---------------------------------------------------------------------------
__device__ __forceinline__ uint32_t smem_u32(const void* p) {
    return (uint32_t)__cvta_generic_to_shared(p);
}
__device__ __forceinline__ void ldsm_x4(uint32_t& r0, uint32_t& r1,
                                        uint32_t& r2, uint32_t& r3, uint32_t addr) {
    asm volatile("ldmatrix.sync.aligned.m8n8.x4.shared.b16 {%0,%1,%2,%3},[%4];"
                 : "=r"(r0), "=r"(r1), "=r"(r2), "=r"(r3) : "r"(addr));
}
__device__ __forceinline__ void ldsm_x4_t(uint32_t& r0, uint32_t& r1,
                                          uint32_t& r2, uint32_t& r3, uint32_t addr) {
    asm volatile("ldmatrix.sync.aligned.m8n8.x4.trans.shared.b16 {%0,%1,%2,%3},[%4];"
                 : "=r"(r0), "=r"(r1), "=r"(r2), "=r"(r3) : "r"(addr));
}
__device__ __forceinline__ void mma_bf16(float* c,
                                         uint32_t a0, uint32_t a1, uint32_t a2, uint32_t a3,
                                         uint32_t b0, uint32_t b1) {
    asm volatile("mma.sync.aligned.m16n8k16.row.col.f32.bf16.bf16.f32 "
                 "{%0,%1,%2,%3},{%4,%5,%6,%7},{%8,%9},{%0,%1,%2,%3};"
                 : "+f"(c[0]), "+f"(c[1]), "+f"(c[2]), "+f"(c[3])
                 : "r"(a0), "r"(a1), "r"(a2), "r"(a3), "r"(b0), "r"(b1));
}
__device__ __forceinline__ uint32_t pack_bf2(float lo, float hi) {
    __nv_bfloat162 t = __floats2bfloat162_rn(lo, hi);
    return *(uint32_t*)&t;
}
__device__ __forceinline__ void split2(float a, float b, uint32_t& hi, uint32_t& lo) {
    __nv_bfloat16 ha = __float2bfloat16(a);
    __nv_bfloat16 hb = __float2bfloat16(b);
    hi = (uint32_t)__bfloat16_as_ushort(ha) | ((uint32_t)__bfloat16_as_ushort(hb) << 16);
    lo = pack_bf2(a - __bfloat162float(ha), b - __bfloat162float(hb));
}
__device__ __forceinline__ void split_pack(float4 f, uint32_t& h01, uint32_t& h23,
                                           uint32_t& l01, uint32_t& l23) {
    split2(f.x, f.y, h01, l01);
    split2(f.z, f.w, h23, l23);
}

#define CP16(dst, src) asm volatile("cp.async.cg.shared.global [%0],[%1],16;" :: "r"(dst), "l"(src))
#define CPCOMMIT()     asm volatile("cp.async.commit_group;")
#define CPWAIT1()      asm volatile("cp.async.wait_group 1;")
#define CPWAIT0()      asm volatile("cp.async.wait_group 0;")

// ---------------------------------------------------------------------------
// Kernel 1 (merged): blocks [0, TOKENS) do LayerNorm+split on x rows;
// blocks [TOKENS, TOKENS+4096) split the 4 weight matrices.
// ---------------------------------------------------------------------------
__global__ __launch_bounds__(256) void prep_split(const float* __restrict__ x,
                                                  const float* __restrict__ W0,
                                                  const float* __restrict__ W1,
                                                  const float* __restrict__ W2,
                                                  const float* __restrict__ W3,
                                                  uint16_t* __restrict__ yh,
                                                  uint16_t* __restrict__ yl,
                                                  uint16_t* __restrict__ wh,
                                                  uint16_t* __restrict__ wl)
{
    int t = threadIdx.x;
    if (blockIdx.x < TOKENS) {
        int row = blockIdx.x;
        const float4* xr = (const float4*)(x + (size_t)row * CH);

        float4 v = xr[t];
        float s  = v.x + v.y + v.z + v.w;
        float ss = v.x*v.x + v.y*v.y + v.z*v.z + v.w*v.w;

        #pragma unroll
        for (int o = 16; o; o >>= 1) {
            s  += __shfl_xor_sync(0xFFFFFFFFu, s,  o);
            ss += __shfl_xor_sync(0xFFFFFFFFu, ss, o);
        }
        __shared__ float sh[16];
        int w = t >> 5, l = t & 31;
        if (l == 0) { sh[w] = s; sh[8 + w] = ss; }
        __syncthreads();
        float S = 0.f, SS = 0.f;
        #pragma unroll
        for (int i = 0; i < 8; i++) { S += sh[i]; SS += sh[8 + i]; }

        float mean = S * (1.0f / CH);
        float var  = SS * (1.0f / CH) - mean * mean;
        float inv  = rsqrtf(var + LN_EPS);

        v.x = (v.x - mean) * inv;
        v.y = (v.y - mean) * inv;
        v.z = (v.z - mean) * inv;
        v.w = (v.w - mean) * inv;

        uint32_t h01, h23, l01, l23;
        split_pack(v, h01, h23, l01, l23);
        size_t off = (size_t)row * CH + t * 4;
        *(uint2*)(yh + off) = make_uint2(h01, h23);
        *(uint2*)(yl + off) = make_uint2(l01, l23);
    } else {
        int wid = blockIdx.x - TOKENS;        // 0..4095
        int z   = wid >> 10;                  // weight matrix 0..3
        int blk = wid & 1023;                 // block within matrix
        const float* W = (z == 0) ? W0 : (z == 1) ? W1 : (z == 2) ? W2 : W3;
        size_t base = (size_t)z * CH * CH;
        size_t off  = ((size_t)blk * 256 + t) * 4;

        float4 f = *(const float4*)(W + off);
        uint32_t h01, h23, l01, l23;
        split_pack(f, h01, h23, l01, l23);
        *(uint2*)(wh + base + off) = make_uint2(h01, h23);
        *(uint2*)(wl + base + off) = make_uint2(l01, l23);
    }
}

// ---------------------------------------------------------------------------
// Kernel 2: pure-bf16 tensor-core GEMM (NT), cp.async double-buffered.
// R12 mainloop EXACTLY (2-stage, 128x128x32, warp tile 64x32, A upfront,
// chain-order mma, __launch_bounds__(256,2)).
// QKV3 epilogue: smem-staged fused head-LN + split. !QKV3: fp32 + bias.
// ---------------------------------------------------------------------------
#define BK    32
#define PADK  40
#define PLANE (128*PADK)   // bf16 elements per smem plane
#define EPAD  132          // epilogue staging row stride (floats, mult of 4)

template<bool QKV3>
__global__ __launch_bounds__(256, 2) void gemm_async(const uint16_t* __restrict__ Ah,
                                                     const uint16_t* __restrict__ Al,
                                                     const uint16_t* __restrict__ Bh_,
                                                     const uint16_t* __restrict__ Bl_,
                                                     const float* __restrict__ bias,
                                                     float* __restrict__ C,
                                                     uint16_t* __restrict__ pqh,
                                                     uint16_t* __restrict__ pql,
                                                     uint16_t* __restrict__ pkh,
                                                     uint16_t* __restrict__ pkl,
                                                     uint16_t* __restrict__ pvh,
                                                     uint16_t* __restrict__ pvl)
{
    extern __shared__ __align__(16) uint16_t smg[];

    int z = QKV3 ? blockIdx.z : 3;
    const uint16_t* Bh = Bh_;
    const uint16_t* Bl = Bl_;
    if (QKV3) {
        size_t zo = (size_t)z * CH * CH;
        Bh += zo; Bl += zo;
    }

    int t    = threadIdx.x;
    int lane = t & 31;
    int warp = t >> 5;
    int wm64 = (warp >> 2) * 64;
    int wn32 = (warp & 3) * 32;
    int bm = blockIdx.y * 128;
    int bn = blockIdx.x * 128;

    const uint16_t* Agh = Ah + (size_t)bm * CH;
    const uint16_t* Agl = Al + (size_t)bm * CH;
    const uint16_t* Bgh = Bh + (size_t)bn * CH;
    const uint16_t* Bgl = Bl + (size_t)bn * CH;

    uint32_t smem_base = smem_u32(smg);

    float acc[4][4][4];
    #pragma unroll
    for (int i = 0; i < 4; i++)
        #pragma unroll
        for (int j = 0; j < 4; j++)
            #pragma unroll
            for (int c = 0; c < 4; c++) acc[i][j][c] = 0.f;

    // per-thread cp.async chunks: 2 per plane (512 chunks of 16B per plane)
    int c0r = t >> 2,          c0c = (t & 3) * 8;
    int c1r = (t + 256) >> 2,  c1c = ((t + 256) & 3) * 8;

    auto issue = [&](int stage, int k0) {
        uint32_t sb = smem_base + stage * (4 * PLANE * 2);
        uint32_t s0 = sb + (c0r * PADK + c0c) * 2;
        uint32_t s1 = sb + (c1r * PADK + c1c) * 2;
        CP16(s0 + 0*PLANE*2, Agh + (size_t)c0r * CH + k0 + c0c);
        CP16(s1 + 0*PLANE*2, Agh + (size_t)c1r * CH + k0 + c1c);
        CP16(s0 + 1*PLANE*2, Agl + (size_t)c0r * CH + k0 + c0c);
        CP16(s1 + 1*PLANE*2, Agl + (size_t)c1r * CH + k0 + c1c);
        CP16(s0 + 2*PLANE*2, Bgh + (size_t)c0r * CH + k0 + c0c);
        CP16(s1 + 2*PLANE*2, Bgh + (size_t)c1r * CH + k0 + c1c);
        CP16(s0 + 3*PLANE*2, Bgl + (size_t)c0r * CH + k0 + c0c);
        CP16(s1 + 3*PLANE*2, Bgl + (size_t)c1r * CH + k0 + c1c);
        CPCOMMIT();
    };

    int a_r    = lane & 15;
    int a_koff = (lane >> 4) << 3;
    int b_n    = (lane & 7) + ((lane >> 4) << 3);
    int b_koff = ((lane >> 3) & 1) << 3;

    const int T = CH / BK;   // 32
    issue(0, 0);
    issue(1, BK);

    for (int i = 0; i < T; i++) {
        if (i + 1 < T) { CPWAIT1(); } else { CPWAIT0(); }
        __syncthreads();

        uint16_t* sAh = smg + (i & 1) * 4 * PLANE;
        uint16_t* sAl = sAh + PLANE;
        uint16_t* sBh = sAl + PLANE;
        uint16_t* sBl = sBh + PLANE;

        #pragma unroll
        for (int kc = 0; kc < 2; kc++) {
            int ko = kc * 16;
            uint32_t ah[4][4], al[4][4], bh[4][2], bl[4][2];
            #pragma unroll
            for (int mt = 0; mt < 4; mt++) {
                int off = (wm64 + mt * 16 + a_r) * PADK + ko + a_koff;
                ldsm_x4(ah[mt][0], ah[mt][1], ah[mt][2], ah[mt][3], smem_u32(&sAh[off]));
                ldsm_x4(al[mt][0], al[mt][1], al[mt][2], al[mt][3], smem_u32(&sAl[off]));
            }
            #pragma unroll
            for (int p = 0; p < 2; p++) {
                int off = (wn32 + p * 16 + b_n) * PADK + ko + b_koff;
                uint32_t r0, r1, r2, r3;
                ldsm_x4(r0, r1, r2, r3, smem_u32(&sBh[off]));
                bh[2*p][0] = r0; bh[2*p][1] = r1; bh[2*p+1][0] = r2; bh[2*p+1][1] = r3;
                ldsm_x4(r0, r1, r2, r3, smem_u32(&sBl[off]));
                bl[2*p][0] = r0; bl[2*p][1] = r1; bl[2*p+1][0] = r2; bl[2*p+1][1] = r3;
            }
            #pragma unroll
            for (int mt = 0; mt < 4; mt++)
                #pragma unroll
                for (int nt = 0; nt < 4; nt++) {
                    float* c = acc[mt][nt];
                    mma_bf16(c, ah[mt][0], ah[mt][1], ah[mt][2], ah[mt][3],
                             bh[nt][0], bh[nt][1]);
                    mma_bf16(c, ah[mt][0], ah[mt][1], ah[mt][2], ah[mt][3],
                             bl[nt][0], bl[nt][1]);
                    mma_bf16(c, al[mt][0], al[mt][1], al[mt][2], al[mt][3],
                             bh[nt][0], bh[nt][1]);
                }
        }
        __syncthreads();
        if (i + 2 < T) issue(i & 1, (i + 2) * BK);
    }

    int lane4 = lane >> 2;
    int lpair = (lane & 3) * 2;

    if (QKV3) {
        // ---- stage fp32 tile to smem (reuse pipeline buffer; 128x132 floats) ----
        float* st = (float*)smg;
        #pragma unroll
        for (int mt = 0; mt < 4; mt++) {
            int r0 = wm64 + mt * 16 + lane4;
            #pragma unroll
            for (int nt = 0; nt < 4; nt++) {
                int col = wn32 + nt * 8 + lpair;
                float* c = acc[mt][nt];
                *(float2*)&st[(size_t)r0 * EPAD + col]       = make_float2(c[0], c[1]);
                *(float2*)&st[(size_t)(r0 + 8) * EPAD + col] = make_float2(c[2], c[3]);
            }
        }
        __syncthreads();

        // ---- thread-per-(row, head): LN + split + coalesced plane write ----
        uint16_t* dh = (z == 0) ? pqh : (z == 1) ? pkh : pvh;
        uint16_t* dl = (z == 0) ? pql : (z == 1) ? pkl : pvl;
        float sc = (z == 0) ? QSCALE : 1.0f;

        int r   = t >> 1;                 // 0..127 tile row
        int hh  = t & 1;                  // which head half of the 128 cols
        const float* v = st + (size_t)r * EPAD + hh * 64;

        float mean = 0.f, inv = 1.f;
        if (z < 2) {
            float s = 0.f, ss = 0.f;
            #pragma unroll
            for (int j = 0; j < 16; j++) {
                float4 f = *(const float4*)(v + j * 4);
                s  += (f.x + f.y) + (f.z + f.w);
                ss += (f.x*f.x + f.y*f.y) + (f.z*f.z + f.w*f.w);
            }
            mean = s * (1.0f / DH);
            float var = ss * (1.0f / DH) - mean * mean;
            inv = rsqrtf(var + LN_EPS) * sc;
        }

        int row = bm + r;
        int bb  = row >> 10, n = row & 1023;
        int h   = blockIdx.x * 2 + hh;
        size_t base = (((size_t)(bb * HEADS + h)) * SEQ + n) * DH;
        #pragma unroll
        for (int j = 0; j < 16; j++) {
            float4 f = *(const float4*)(v + j * 4);
            f.x = (f.x - mean) * inv; f.y = (f.y - mean) * inv;
            f.z = (f.z - mean) * inv; f.w = (f.w - mean) * inv;
            uint32_t h01, h23, l01, l23;
            split_pack(f, h01, h23, l01, l23);
            *(uint2*)(dh + base + j * 4) = make_uint2(h01, h23);
            *(uint2*)(dl + base + j * 4) = make_uint2(l01, l23);
        }
    } else {
        // out-projection: fp32 + bias, direct
        #pragma unroll
        for (int mt = 0; mt < 4; mt++) {
            int row = bm + wm64 + mt * 16 + lane4;
            #pragma unroll
            for (int nt = 0; nt < 4; nt++) {
                int col = bn + wn32 + nt * 8 + lpair;
                float b0 = bias[col], b1 = bias[col + 1];
                float* c = acc[mt][nt];
                *(float2*)(C + (size_t)row * CH + col)       = make_float2(c[0] + b0, c[1] + b1);
                *(float2*)(C + (size_t)(row + 8) * CH + col) = make_float2(c[2] + b0, c[3] + b1);
            }
        }
    }
}

// ---------------------------------------------------------------------------
// Kernel 3: tensor-core flash attention (no max tracking: |s|<=8).
// Q fragments re-ldsm'd per ch (frees regs); __launch_bounds__(256, 2)
// -> 128 regs -> 2 CTAs/SM. 3-pass QK^T; 3-pass P*V; KV double-buffered.
// ---------------------------------------------------------------------------
#define SSTR    72
#define KV_B    (4*64*SSTR)        // bf16 elements per KV stage

__global__ __launch_bounds__(256, 2) void attn_tc(const uint16_t* __restrict__ qh,
                                                  const uint16_t* __restrict__ ql,
                                                  const uint16_t* __restrict__ kh,
                                                  const uint16_t* __restrict__ kl,
                                                  const uint16_t* __restrict__ vh,
                                                  const uint16_t* __restrict__ vl,
                                                  uint16_t* __restrict__ aoh,
                                                  uint16_t* __restrict__ aol)
{
    extern __shared__ __align__(16) uint16_t sm[];
    uint16_t* Qh = sm;                       // 128*SSTR
    uint16_t* Ql = Qh + 128 * SSTR;
    uint16_t* KV = Ql + 128 * SSTR;          // 2 stages of KV_B

    int bh = blockIdx.x;
    int qb = blockIdx.y * 128;
    int t = threadIdx.x, lane = t & 31, warp = t >> 5;
    size_t plane = (size_t)bh * SEQ * DH;

    int k0r = t >> 3,         k0c = (t & 7) * 8;
    int k1r = (t + 256) >> 3, k1c = ((t + 256) & 7) * 8;
    uint32_t kv_base = smem_u32(KV);

    auto issue_kv = [&](int stage, int kt) {
        uint32_t sb = kv_base + stage * (KV_B * 2);
        uint32_t s0 = sb + (k0r * SSTR + k0c) * 2;
        uint32_t s1 = sb + (k1r * SSTR + k1c) * 2;
        size_t g0 = plane + (size_t)(kt + k0r) * DH + k0c;
        size_t g1 = plane + (size_t)(kt + k1r) * DH + k1c;
        const int PL = 64 * SSTR * 2;
        CP16(s0 + 0*PL, kh + g0);  CP16(s1 + 0*PL, kh + g1);
        CP16(s0 + 1*PL, kl + g0);  CP16(s1 + 1*PL, kl + g1);
        CP16(s0 + 2*PL, vh + g0);  CP16(s1 + 2*PL, vh + g1);
        CP16(s0 + 3*PL, vl + g0);  CP16(s1 + 3*PL, vl + g1);
        CPCOMMIT();
    };

    issue_kv(0, 0);
    issue_kv(1, 64);

    #pragma unroll
    for (int i = 0; i < 4; i++) {
        int f = t + i * 256;
        int row = f >> 3, c = (f & 7) * 8;
        size_t src = plane + (size_t)(qb + row) * DH + c;
        *(uint4*)&Qh[row * SSTR + c] = *(const uint4*)(qh + src);
        *(uint4*)&Ql[row * SSTR + c] = *(const uint4*)(ql + src);
    }
    __syncthreads();

    int a_r = lane & 15, a_ko = (lane >> 4) << 3;

    float oacc[8][4];
    #pragma unroll
    for (int i = 0; i < 8; i++)
        #pragma unroll
        for (int j = 0; j < 4; j++) oacc[i][j] = 0.f;
    float l0 = 0.f, l1 = 0.f;

    int b_n  = (lane & 7) + ((lane >> 4) << 3);
    int b_ko = ((lane >> 3) & 1) << 3;
    int v_r  = lane & 15;
    int v_co = (lane >> 4) * 8;

    const int T = SEQ / 64;
    for (int i = 0; i < T; i++) {
        if (i + 1 < T) { CPWAIT1(); } else { CPWAIT0(); }
        __syncthreads();

        uint16_t* Kh = KV + (i & 1) * KV_B;
        uint16_t* Kl = Kh + 64 * SSTR;
        uint16_t* Vh = Kl + 64 * SSTR;
        uint16_t* Vl = Vh + 64 * SSTR;

        float sacc[8][4];
        #pragma unroll
        for (int a = 0; a < 8; a++)
            #pragma unroll
            for (int c = 0; c < 4; c++) sacc[a][c] = 0.f;

        // ----- S = Q K^T (3-pass), ch-outer; Q fragments re-ldsm'd per ch -----
        #pragma unroll
        for (int ch = 0; ch < 4; ch++) {
            uint32_t q0,q1,q2,q3, e0,e1,e2,e3;
            int qoff = (warp * 16 + a_r) * SSTR + ch * 16 + a_ko;
            ldsm_x4(q0,q1,q2,q3, smem_u32(&Qh[qoff]));
            ldsm_x4(e0,e1,e2,e3, smem_u32(&Ql[qoff]));
            #pragma unroll
            for (int kp = 0; kp < 4; kp++) {
                int off = (kp * 16 + b_n) * SSTR + ch * 16 + b_ko;
                uint32_t h0,h1,h2,h3, f0,f1,f2,f3;
                ldsm_x4(h0,h1,h2,h3, smem_u32(&Kh[off]));
                ldsm_x4(f0,f1,f2,f3, smem_u32(&Kl[off]));
                float* c0 = sacc[2*kp];
                float* c1 = sacc[2*kp+1];
                mma_bf16(c0, q0,q1,q2,q3, h0,h1);
                mma_bf16(c1, q0,q1,q2,q3, h2,h3);
                mma_bf16(c0, q0,q1,q2,q3, f0,f1);
                mma_bf16(c1, q0,q1,q2,q3, f2,f3);
                mma_bf16(c0, e0,e1,e2,e3, h0,h1);
                mma_bf16(c1, e0,e1,e2,e3, h2,h3);
            }
        }

        // ----- exp + l accumulation -----
        #pragma unroll
        for (int nt = 0; nt < 8; nt++) {
            float p0 = __expf(sacc[nt][0]);
            float p1 = __expf(sacc[nt][1]);
            float p2 = __expf(sacc[nt][2]);
            float p3 = __expf(sacc[nt][3]);
            sacc[nt][0] = p0; sacc[nt][1] = p1;
            sacc[nt][2] = p2; sacc[nt][3] = p3;
            l0 += p0 + p1;
            l1 += p2 + p3;
        }

        // ----- O += P V (3-pass) -----
        #pragma unroll
        for (int j = 0; j < 4; j++) {
            uint32_t ph[4], pl[4];
            float* ca = sacc[2*j];
            float* cb = sacc[2*j+1];
            split2(ca[0], ca[1], ph[0], pl[0]);
            split2(ca[2], ca[3], ph[1], pl[1]);
            split2(cb[0], cb[1], ph[2], pl[2]);
            split2(cb[2], cb[3], ph[3], pl[3]);
            #pragma unroll
            for (int dp = 0; dp < 4; dp++) {
                int off = (j * 16 + v_r) * SSTR + dp * 16 + v_co;
                uint32_t b0,b1,b2,b3, f0,f1,f2,f3;
                ldsm_x4_t(b0,b1,b2,b3, smem_u32(&Vh[off]));
                ldsm_x4_t(f0,f1,f2,f3, smem_u32(&Vl[off]));
                float* o0 = oacc[2*dp];
                float* o1 = oacc[2*dp+1];
                mma_bf16(o0, ph[0],ph[1],ph[2],ph[3], b0,b1);
                mma_bf16(o0, ph[0],ph[1],ph[2],ph[3], f0,f1);
                mma_bf16(o0, pl[0],pl[1],pl[2],pl[3], b0,b1);
                mma_bf16(o1, ph[0],ph[1],ph[2],ph[3], b2,b3);
                mma_bf16(o1, ph[0],ph[1],ph[2],ph[3], f2,f3);
                mma_bf16(o1, pl[0],pl[1],pl[2],pl[3], b2,b3);
            }
        }

        __syncthreads();
        if (i + 2 < T) issue_kv(i & 1, (i + 2) * 64);
    }

    l0 += __shfl_xor_sync(0xFFFFFFFFu, l0, 1);
    l0 += __shfl_xor_sync(0xFFFFFFFFu, l0, 2);
    l1 += __shfl_xor_sync(0xFFFFFFFFu, l1, 1);
    l1 += __shfl_xor_sync(0xFFFFFFFFu, l1, 2);
    float rl0 = 1.0f / l0, rl1 = 1.0f / l1;

    int b = bh >> 4, h = bh & 15;
    int r0 = qb + warp * 16 + (lane >> 2);
    size_t base0 = ((size_t)(b * SEQ + r0)) * CH + h * DH + (lane & 3) * 2;
    size_t base1 = base0 + 8 * CH;
    #pragma unroll
    for (int nt = 0; nt < 8; nt++) {
        uint32_t hi, lo;
        split2(oacc[nt][0] * rl0, oacc[nt][1] * rl0, hi, lo);
        *(uint32_t*)(aoh + base0 + nt * 8) = hi;
        *(uint32_t*)(aol + base0 + nt * 8) = lo;
        split2(oacc[nt][2] * rl1, oacc[nt][3] * rl1, hi, lo);
        *(uint32_t*)(aoh + base1 + nt * 8) = hi;
        *(uint32_t*)(aol + base1 + nt * 8) = lo;
    }
}

// ---------------------------------------------------------------------------
// Launch
// ---------------------------------------------------------------------------
extern "C" void kernel_launch(void* const* d_in, const int* in_sizes, int n_in,
                              void* d_out, int out_size)
{
    const float* x  = (const float*)d_in[0];
    const float* Wq = (const float*)d_in[1];
    const float* Wk = (const float*)d_in[2];
    const float* Wv = (const float*)d_in[3];
    const float* Wp = (const float*)d_in[4];
    const float* bp = (const float*)d_in[5];
    float* out = (float*)d_out;

    uint16_t *p_yh, *p_yl, *p_wh, *p_wl;
    uint16_t *p_qh, *p_ql, *p_kh, *p_kl, *p_vh, *p_vl, *p_aoh, *p_aol;
    cudaGetSymbolAddress((void**)&p_yh, g_yh);
    cudaGetSymbolAddress((void**)&p_yl, g_yl);
    cudaGetSymbolAddress((void**)&p_wh, g_wh);
    cudaGetSymbolAddress((void**)&p_wl, g_wl);
    cudaGetSymbolAddress((void**)&p_qh, g_qh);
    cudaGetSymbolAddress((void**)&p_ql, g_ql);
    cudaGetSymbolAddress((void**)&p_kh, g_kh);
    cudaGetSymbolAddress((void**)&p_kl, g_kl);
    cudaGetSymbolAddress((void**)&p_vh, g_vh);
    cudaGetSymbolAddress((void**)&p_vl, g_vl);
    cudaGetSymbolAddress((void**)&p_aoh, g_aoh);
    cudaGetSymbolAddress((void**)&p_aol, g_aol);

    const int GEMM_SMEM = 2 * 4 * PLANE * 2;                   // 81920 B
    const int ATT_SMEM  = (2 * 128 * SSTR + 2 * KV_B) * 2;     // 110592 B
    static int configured = 0;
    if (!configured) {
        cudaFuncSetAttribute(gemm_async<true>,
                             cudaFuncAttributeMaxDynamicSharedMemorySize, GEMM_SMEM);
        cudaFuncSetAttribute(gemm_async<false>,
                             cudaFuncAttributeMaxDynamicSharedMemorySize, GEMM_SMEM);
        cudaFuncSetAttribute(attn_tc,
                             cudaFuncAttributeMaxDynamicSharedMemorySize, ATT_SMEM);
        configured = 1;
    }

    // 1. Pre-LN + weight split in one merged launch
    prep_split<<<TOKENS + 4 * CH * CH / 1024, 256>>>(x, Wq, Wk, Wv, Wp,
                                                     p_yh, p_yl, p_wh, p_wl);

    // 2. QKV projections with fused head-LN + split epilogue (smem-staged)
    dim3 gqkv(CH / 128, TOKENS / 128, 3);
    gemm_async<true><<<gqkv, 256, GEMM_SMEM>>>(p_yh, p_yl, p_wh, p_wl,
                                               nullptr, nullptr,
                                               p_qh, p_ql, p_kh, p_kl, p_vh, p_vl);

    // 3. Tensor-core flash attention (writes split planes)
    attn_tc<<<dim3(BATCH * HEADS, SEQ / 128), 256, ATT_SMEM>>>(p_qh, p_ql, p_kh, p_kl,
                                                               p_vh, p_vl, p_aoh, p_aol);

    // 4. Output projection + bias
    dim3 gout(CH / 128, TOKENS / 128, 1);
    gemm_async<false><<<gout, 256, GEMM_SMEM>>>(p_aoh, p_aol,
                                                p_wh + (size_t)3 * CH * CH,
                                                p_wl + (size_t)3 * CH * CH,
                                                bp, out,
                                                nullptr, nullptr, nullptr, nullptr,
                                                nullptr, nullptr);
}

// round 15
// speedup vs baseline: 1.3733x; 1.3528x over previous
#include <cuda_runtime.h>
#include <cuda_fp16.h>
#include <math.h>
#include <stdint.h>

// Problem constants
#define BATCH   16
#define SEQ     1024
#define CH      1024
#define HEADS   16
#define DH      64
#define TOKENS  (BATCH*SEQ)      // 16384
#define LN_EPS  1e-6f
#define QSCALE  0.125f           // Dh^-0.5
#define WSCALE  64.0f            // weight pre-scale (keeps w_lo fp16-normal)
#define WINV    (1.0f/64.0f)

// Scratch (device globals: allocation-free per harness rules)
__device__ uint16_t g_yh[TOKENS*CH];                          // y hi only
__device__ uint16_t g_wh[4*CH*CH];   __device__ uint16_t g_wl[4*CH*CH];
// per-head planes [B,H,N,DH]
__device__ uint16_t g_qh[TOKENS*CH];                          // q hi only
__device__ uint16_t g_kh[TOKENS*CH]; __device__ uint16_t g_kl[TOKENS*CH];
__device__ uint16_t g_vh[TOKENS*CH]; __device__ uint16_t g_vl[TOKENS*CH];
// attention output (hi only) in [token][CH] layout
__device__ uint16_t g_aoh[TOKENS*CH];

// ---------------------------------------------------------------------------
// helpers
// ---------------------------------------------------------------------------
__device__ __forceinline__ uint32_t smem_u32(const void* p) {
    return (uint32_t)__cvta_generic_to_shared(p);
}
__device__ __forceinline__ void ldsm_x4(uint32_t& r0, uint32_t& r1,
                                        uint32_t& r2, uint32_t& r3, uint32_t addr) {
    asm volatile("ldmatrix.sync.aligned.m8n8.x4.shared.b16 {%0,%1,%2,%3},[%4];"
                 : "=r"(r0), "=r"(r1), "=r"(r2), "=r"(r3) : "r"(addr));
}
__device__ __forceinline__ void ldsm_x4_t(uint32_t& r0, uint32_t& r1,
                                          uint32_t& r2, uint32_t& r3, uint32_t addr) {
    asm volatile("ldmatrix.sync.aligned.m8n8.x4.trans.shared.b16 {%0,%1,%2,%3},[%4];"
                 : "=r"(r0), "=r"(r1), "=r"(r2), "=r"(r3) : "r"(addr));
}
__device__ __forceinline__ void mma_f16(float* c,
                                        uint32_t a0, uint32_t a1, uint32_t a2, uint32_t a3,
                                        uint32_t b0, uint32_t b1) {
    asm volatile("mma.sync.aligned.m16n8k16.row.col.f32.f16.f16.f32 "
                 "{%0,%1,%2,%3},{%4,%5,%6,%7},{%8,%9},{%0,%1,%2,%3};"
                 : "+f"(c[0]), "+f"(c[1]), "+f"(c[2]), "+f"(c[3])
                 : "r"(a0), "r"(a1), "r"(a2), "r"(a3), "r"(b0), "r"(b1));
}
__device__ __forceinline__ uint32_t pack_h2(float a, float b) {
    __half2 h = __floats2half2_rn(a, b);
    return *(uint32_t*)&h;
}
__device__ __forceinline__ void split2h(float a, float b, uint32_t& hi, uint32_t& lo) {
    __half2 h = __floats2half2_rn(a, b);
    float ra = a - __half2float(__low2half(h));
    float rb = b - __half2float(__high2half(h));
    hi = *(uint32_t*)&h;
    lo = pack_h2(ra, rb);
}

#define CP16(dst, src) asm volatile("cp.async.cg.shared.global [%0],[%1],16;" :: "r"(dst), "l"(src))
#define CPCOMMIT()     asm volatile("cp.async.commit_group;")
#define CPWAIT1()      asm volatile("cp.async.wait_group 1;")
#define CPWAIT0()      asm volatile("cp.async.wait_group 0;")

// ---------------------------------------------------------------------------
// Kernel 1 (merged): blocks [0, TOKENS) do LayerNorm on x rows -> yh (fp16 hi).
// blocks [TOKENS, TOKENS+4096) split the 4 weight matrices x64 -> wh+wl.
// ---------------------------------------------------------------------------
__global__ __launch_bounds__(256) void prep_split(const float* __restrict__ x,
                                                  const float* __restrict__ W0,
                                                  const float* __restrict__ W1,
                                                  const float* __restrict__ W2,
                                                  const float* __restrict__ W3,
                                                  uint16_t* __restrict__ yh,
                                                  uint16_t* __restrict__ wh,
                                                  uint16_t* __restrict__ wl)
{
    int t = threadIdx.x;
    if (blockIdx.x < TOKENS) {
        int row = blockIdx.x;
        const float4* xr = (const float4*)(x + (size_t)row * CH);

        float4 v = xr[t];
        float s  = v.x + v.y + v.z + v.w;
        float ss = v.x*v.x + v.y*v.y + v.z*v.z + v.w*v.w;

        #pragma unroll
        for (int o = 16; o; o >>= 1) {
            s  += __shfl_xor_sync(0xFFFFFFFFu, s,  o);
            ss += __shfl_xor_sync(0xFFFFFFFFu, ss, o);
        }
        __shared__ float sh[16];
        int w = t >> 5, l = t & 31;
        if (l == 0) { sh[w] = s; sh[8 + w] = ss; }
        __syncthreads();
        float S = 0.f, SS = 0.f;
        #pragma unroll
        for (int i = 0; i < 8; i++) { S += sh[i]; SS += sh[8 + i]; }

        float mean = S * (1.0f / CH);
        float var  = SS * (1.0f / CH) - mean * mean;
        float inv  = rsqrtf(var + LN_EPS);

        uint32_t h01 = pack_h2((v.x - mean) * inv, (v.y - mean) * inv);
        uint32_t h23 = pack_h2((v.z - mean) * inv, (v.w - mean) * inv);
        *(uint2*)(yh + (size_t)row * CH + t * 4) = make_uint2(h01, h23);
    } else {
        int wid = blockIdx.x - TOKENS;        // 0..4095
        int z   = wid >> 10;
        int blk = wid & 1023;
        const float* W = (z == 0) ? W0 : (z == 1) ? W1 : (z == 2) ? W2 : W3;
        size_t base = (size_t)z * CH * CH;
        size_t off  = ((size_t)blk * 256 + t) * 4;

        float4 f = *(const float4*)(W + off);
        uint32_t h01, h23, l01, l23;
        split2h(f.x * WSCALE, f.y * WSCALE, h01, l01);
        split2h(f.z * WSCALE, f.w * WSCALE, h23, l23);
        *(uint2*)(wh + base + off) = make_uint2(h01, h23);
        *(uint2*)(wl + base + off) = make_uint2(l01, l23);
    }
}

// ---------------------------------------------------------------------------
// Kernel 2: fp16 tensor-core GEMM (NT), cp.async double-buffered.
// A hi-only, B hi+lo (weights x64). 2-pass: a*bh + a*bl.
// 2-stage, 128x128x32, warp tile 64x32, __launch_bounds__(256,2).
// QKV3 epilogue (smem-staged, thread-per-(row,head)):
//   z=0: head-LN (scale-invariant, washes out x64) * QSCALE -> qh only
//   z=1: head-LN -> kh + kl
//   z=2: passthrough /64 -> vh + vl
// !QKV3: out = C/64 + bias (fp32).
// ---------------------------------------------------------------------------
#define BK    32
#define PADK  40
#define PLANE (128*PADK)   // fp16 elements per smem plane
#define EPAD  132          // epilogue staging row stride (floats, mult of 4)

template<bool QKV3>
__global__ __launch_bounds__(256, 2) void gemm_async(const uint16_t* __restrict__ Ah,
                                                     const uint16_t* __restrict__ Bh_,
                                                     const uint16_t* __restrict__ Bl_,
                                                     const float* __restrict__ bias,
                                                     float* __restrict__ C,
                                                     uint16_t* __restrict__ pqh,
                                                     uint16_t* __restrict__ pkh,
                                                     uint16_t* __restrict__ pkl,
                                                     uint16_t* __restrict__ pvh,
                                                     uint16_t* __restrict__ pvl)
{
    extern __shared__ __align__(16) uint16_t smg[];

    int z = QKV3 ? blockIdx.z : 3;
    const uint16_t* Bh = Bh_;
    const uint16_t* Bl = Bl_;
    if (QKV3) {
        size_t zo = (size_t)z * CH * CH;
        Bh += zo; Bl += zo;
    }

    int t    = threadIdx.x;
    int lane = t & 31;
    int warp = t >> 5;
    int wm64 = (warp >> 2) * 64;
    int wn32 = (warp & 3) * 32;
    int bm = blockIdx.y * 128;
    int bn = blockIdx.x * 128;

    const uint16_t* Agh = Ah + (size_t)bm * CH;
    const uint16_t* Bgh = Bh + (size_t)bn * CH;
    const uint16_t* Bgl = Bl + (size_t)bn * CH;

    uint32_t smem_base = smem_u32(smg);

    float acc[4][4][4];
    #pragma unroll
    for (int i = 0; i < 4; i++)
        #pragma unroll
        for (int j = 0; j < 4; j++)
            #pragma unroll
            for (int c = 0; c < 4; c++) acc[i][j][c] = 0.f;

    // per-thread cp.async chunks: 2 per plane (512 chunks of 16B per plane)
    int c0r = t >> 2,          c0c = (t & 3) * 8;
    int c1r = (t + 256) >> 2,  c1c = ((t + 256) & 3) * 8;

    auto issue = [&](int stage, int k0) {
        uint32_t sb = smem_base + stage * (3 * PLANE * 2);
        uint32_t s0 = sb + (c0r * PADK + c0c) * 2;
        uint32_t s1 = sb + (c1r * PADK + c1c) * 2;
        CP16(s0 + 0*PLANE*2, Agh + (size_t)c0r * CH + k0 + c0c);
        CP16(s1 + 0*PLANE*2, Agh + (size_t)c1r * CH + k0 + c1c);
        CP16(s0 + 1*PLANE*2, Bgh + (size_t)c0r * CH + k0 + c0c);
        CP16(s1 + 1*PLANE*2, Bgh + (size_t)c1r * CH + k0 + c1c);
        CP16(s0 + 2*PLANE*2, Bgl + (size_t)c0r * CH + k0 + c0c);
        CP16(s1 + 2*PLANE*2, Bgl + (size_t)c1r * CH + k0 + c1c);
        CPCOMMIT();
    };

    int a_r    = lane & 15;
    int a_koff = (lane >> 4) << 3;
    int b_n    = (lane & 7) + ((lane >> 4) << 3);
    int b_koff = ((lane >> 3) & 1) << 3;

    const int T = CH / BK;   // 32
    issue(0, 0);
    issue(1, BK);

    for (int i = 0; i < T; i++) {
        if (i + 1 < T) { CPWAIT1(); } else { CPWAIT0(); }
        __syncthreads();

        uint16_t* sA  = smg + (i & 1) * 3 * PLANE;
        uint16_t* sBh = sA + PLANE;
        uint16_t* sBl = sBh + PLANE;

        #pragma unroll
        for (int kc = 0; kc < 2; kc++) {
            int ko = kc * 16;
            uint32_t a[4][4], bh[4][2], bl[4][2];
            #pragma unroll
            for (int mt = 0; mt < 4; mt++) {
                int off = (wm64 + mt * 16 + a_r) * PADK + ko + a_koff;
                ldsm_x4(a[mt][0], a[mt][1], a[mt][2], a[mt][3], smem_u32(&sA[off]));
            }
            #pragma unroll
            for (int p = 0; p < 2; p++) {
                int off = (wn32 + p * 16 + b_n) * PADK + ko + b_koff;
                uint32_t r0, r1, r2, r3;
                ldsm_x4(r0, r1, r2, r3, smem_u32(&sBh[off]));
                bh[2*p][0] = r0; bh[2*p][1] = r1; bh[2*p+1][0] = r2; bh[2*p+1][1] = r3;
                ldsm_x4(r0, r1, r2, r3, smem_u32(&sBl[off]));
                bl[2*p][0] = r0; bl[2*p][1] = r1; bl[2*p+1][0] = r2; bl[2*p+1][1] = r3;
            }
            #pragma unroll
            for (int mt = 0; mt < 4; mt++)
                #pragma unroll
                for (int nt = 0; nt < 4; nt++) {
                    float* c = acc[mt][nt];
                    mma_f16(c, a[mt][0], a[mt][1], a[mt][2], a[mt][3],
                            bh[nt][0], bh[nt][1]);
                    mma_f16(c, a[mt][0], a[mt][1], a[mt][2], a[mt][3],
                            bl[nt][0], bl[nt][1]);
                }
        }
        __syncthreads();
        if (i + 2 < T) issue(i & 1, (i + 2) * BK);
    }

    int lane4 = lane >> 2;
    int lpair = (lane & 3) * 2;

    if (QKV3) {
        // ---- stage fp32 tile to smem ----
        float* st = (float*)smg;
        #pragma unroll
        for (int mt = 0; mt < 4; mt++) {
            int r0 = wm64 + mt * 16 + lane4;
            #pragma unroll
            for (int nt = 0; nt < 4; nt++) {
                int col = wn32 + nt * 8 + lpair;
                float* c = acc[mt][nt];
                *(float2*)&st[(size_t)r0 * EPAD + col]       = make_float2(c[0], c[1]);
                *(float2*)&st[(size_t)(r0 + 8) * EPAD + col] = make_float2(c[2], c[3]);
            }
        }
        __syncthreads();

        // ---- thread-per-(row, head): LN / descale + fp16 write ----
        int r   = t >> 1;
        int hh  = t & 1;
        const float* v = st + (size_t)r * EPAD + hh * 64;

        float mean = 0.f, inv = WINV;       // z==2: passthrough with /64
        if (z < 2) {
            float s = 0.f, ss = 0.f;
            #pragma unroll
            for (int j = 0; j < 16; j++) {
                float4 f = *(const float4*)(v + j * 4);
                s  += (f.x + f.y) + (f.z + f.w);
                ss += (f.x*f.x + f.y*f.y) + (f.z*f.z + f.w*f.w);
            }
            mean = s * (1.0f / DH);
            float var = ss * (1.0f / DH) - mean * mean;
            inv = rsqrtf(var + LN_EPS) * (z == 0 ? QSCALE : 1.0f);
        }

        int row = bm + r;
        int bb  = row >> 10, n = row & 1023;
        int h   = blockIdx.x * 2 + hh;
        size_t base = (((size_t)(bb * HEADS + h)) * SEQ + n) * DH;

        if (z == 0) {
            #pragma unroll
            for (int j = 0; j < 16; j++) {
                float4 f = *(const float4*)(v + j * 4);
                uint32_t h01 = pack_h2((f.x - mean) * inv, (f.y - mean) * inv);
                uint32_t h23 = pack_h2((f.z - mean) * inv, (f.w - mean) * inv);
                *(uint2*)(pqh + base + j * 4) = make_uint2(h01, h23);
            }
        } else {
            uint16_t* dh = (z == 1) ? pkh : pvh;
            uint16_t* dl = (z == 1) ? pkl : pvl;
            #pragma unroll
            for (int j = 0; j < 16; j++) {
                float4 f = *(const float4*)(v + j * 4);
                uint32_t h01, h23, l01, l23;
                split2h((f.x - mean) * inv, (f.y - mean) * inv, h01, l01);
                split2h((f.z - mean) * inv, (f.w - mean) * inv, h23, l23);
                *(uint2*)(dh + base + j * 4) = make_uint2(h01, h23);
                *(uint2*)(dl + base + j * 4) = make_uint2(l01, l23);
            }
        }
    } else {
        // out-projection: C/64 + bias, fp32
        #pragma unroll
        for (int mt = 0; mt < 4; mt++) {
            int row = bm + wm64 + mt * 16 + lane4;
            #pragma unroll
            for (int nt = 0; nt < 4; nt++) {
                int col = bn + wn32 + nt * 8 + lpair;
                float b0 = bias[col], b1 = bias[col + 1];
                float* c = acc[mt][nt];
                *(float2*)(C + (size_t)row * CH + col) =
                    make_float2(c[0] * WINV + b0, c[1] * WINV + b1);
                *(float2*)(C + (size_t)(row + 8) * CH + col) =
                    make_float2(c[2] * WINV + b0, c[3] * WINV + b1);
            }
        }
    }
}

// ---------------------------------------------------------------------------
// Kernel 3: fp16 tensor-core flash attention (no max tracking: |s|<=8).
// Q hi-only resident; QK: q*(kh+kl) 2-pass; PV: p*(vh+vl) 2-pass (p hi-only).
// KV double-buffered cp.async; __launch_bounds__(256,2).
// ---------------------------------------------------------------------------
#define SSTR    72
#define KV_B    (4*64*SSTR)        // fp16 elements per KV stage (kh,kl,vh,vl)

__global__ __launch_bounds__(256, 2) void attn_tc(const uint16_t* __restrict__ qh,
                                                  const uint16_t* __restrict__ kh,
                                                  const uint16_t* __restrict__ kl,
                                                  const uint16_t* __restrict__ vh,
                                                  const uint16_t* __restrict__ vl,
                                                  uint16_t* __restrict__ aoh)
{
    extern __shared__ __align__(16) uint16_t sm[];
    uint16_t* Qh = sm;                       // 128*SSTR
    uint16_t* KV = Qh + 128 * SSTR;          // 2 stages of KV_B

    int bh = blockIdx.x;
    int qb = blockIdx.y * 128;
    int t = threadIdx.x, lane = t & 31, warp = t >> 5;
    size_t plane = (size_t)bh * SEQ * DH;

    int k0r = t >> 3,         k0c = (t & 7) * 8;
    int k1r = (t + 256) >> 3, k1c = ((t + 256) & 7) * 8;
    uint32_t kv_base = smem_u32(KV);

    auto issue_kv = [&](int stage, int kt) {
        uint32_t sb = kv_base + stage * (KV_B * 2);
        uint32_t s0 = sb + (k0r * SSTR + k0c) * 2;
        uint32_t s1 = sb + (k1r * SSTR + k1c) * 2;
        size_t g0 = plane + (size_t)(kt + k0r) * DH + k0c;
        size_t g1 = plane + (size_t)(kt + k1r) * DH + k1c;
        const int PL = 64 * SSTR * 2;
        CP16(s0 + 0*PL, kh + g0);  CP16(s1 + 0*PL, kh + g1);
        CP16(s0 + 1*PL, kl + g0);  CP16(s1 + 1*PL, kl + g1);
        CP16(s0 + 2*PL, vh + g0);  CP16(s1 + 2*PL, vh + g1);
        CP16(s0 + 3*PL, vl + g0);  CP16(s1 + 3*PL, vl + g1);
        CPCOMMIT();
    };

    issue_kv(0, 0);
    issue_kv(1, 64);

    // Load Q tile (hi only): 1024 x 16B chunks, 4 per thread
    #pragma unroll
    for (int i = 0; i < 4; i++) {
        int f = t + i * 256;
        int row = f >> 3, c = (f & 7) * 8;
        *(uint4*)&Qh[row * SSTR + c] =
            *(const uint4*)(qh + plane + (size_t)(qb + row) * DH + c);
    }
    __syncthreads();

    int a_r = lane & 15, a_ko = (lane >> 4) << 3;

    float oacc[8][4];
    #pragma unroll
    for (int i = 0; i < 8; i++)
        #pragma unroll
        for (int j = 0; j < 4; j++) oacc[i][j] = 0.f;
    float l0 = 0.f, l1 = 0.f;

    int b_n  = (lane & 7) + ((lane >> 4) << 3);
    int b_ko = ((lane >> 3) & 1) << 3;
    int v_r  = lane & 15;
    int v_co = (lane >> 4) * 8;

    const int T = SEQ / 64;
    for (int i = 0; i < T; i++) {
        if (i + 1 < T) { CPWAIT1(); } else { CPWAIT0(); }
        __syncthreads();

        uint16_t* Kh = KV + (i & 1) * KV_B;
        uint16_t* Kl = Kh + 64 * SSTR;
        uint16_t* Vh = Kl + 64 * SSTR;
        uint16_t* Vl = Vh + 64 * SSTR;

        float sacc[8][4];
        #pragma unroll
        for (int a = 0; a < 8; a++)
            #pragma unroll
            for (int c = 0; c < 4; c++) sacc[a][c] = 0.f;

        // ----- S = Q K^T (2-pass: q*kh + q*kl), ch-outer -----
        #pragma unroll
        for (int ch = 0; ch < 4; ch++) {
            uint32_t q0,q1,q2,q3;
            int qoff = (warp * 16 + a_r) * SSTR + ch * 16 + a_ko;
            ldsm_x4(q0,q1,q2,q3, smem_u32(&Qh[qoff]));
            #pragma unroll
            for (int kp = 0; kp < 4; kp++) {
                int off = (kp * 16 + b_n) * SSTR + ch * 16 + b_ko;
                uint32_t h0,h1,h2,h3, f0,f1,f2,f3;
                ldsm_x4(h0,h1,h2,h3, smem_u32(&Kh[off]));
                ldsm_x4(f0,f1,f2,f3, smem_u32(&Kl[off]));
                float* c0 = sacc[2*kp];
                float* c1 = sacc[2*kp+1];
                mma_f16(c0, q0,q1,q2,q3, h0,h1);
                mma_f16(c1, q0,q1,q2,q3, h2,h3);
                mma_f16(c0, q0,q1,q2,q3, f0,f1);
                mma_f16(c1, q0,q1,q2,q3, f2,f3);
            }
        }

        // ----- exp + l accumulation -----
        #pragma unroll
        for (int nt = 0; nt < 8; nt++) {
            float p0 = __expf(sacc[nt][0]);
            float p1 = __expf(sacc[nt][1]);
            float p2 = __expf(sacc[nt][2]);
            float p3 = __expf(sacc[nt][3]);
            sacc[nt][0] = p0; sacc[nt][1] = p1;
            sacc[nt][2] = p2; sacc[nt][3] = p3;
            l0 += p0 + p1;
            l1 += p2 + p3;
        }

        // ----- O += P V (2-pass: p*vh + p*vl, p hi-only) -----
        #pragma unroll
        for (int j = 0; j < 4; j++) {
            float* ca = sacc[2*j];
            float* cb = sacc[2*j+1];
            uint32_t ph[4];
            ph[0] = pack_h2(ca[0], ca[1]);
            ph[1] = pack_h2(ca[2], ca[3]);
            ph[2] = pack_h2(cb[0], cb[1]);
            ph[3] = pack_h2(cb[2], cb[3]);
            #pragma unroll
            for (int dp = 0; dp < 4; dp++) {
                int off = (j * 16 + v_r) * SSTR + dp * 16 + v_co;
                uint32_t b0,b1,b2,b3, f0,f1,f2,f3;
                ldsm_x4_t(b0,b1,b2,b3, smem_u32(&Vh[off]));
                ldsm_x4_t(f0,f1,f2,f3, smem_u32(&Vl[off]));
                float* o0 = oacc[2*dp];
                float* o1 = oacc[2*dp+1];
                mma_f16(o0, ph[0],ph[1],ph[2],ph[3], b0,b1);
                mma_f16(o1, ph[0],ph[1],ph[2],ph[3], b2,b3);
                mma_f16(o0, ph[0],ph[1],ph[2],ph[3], f0,f1);
                mma_f16(o1, ph[0],ph[1],ph[2],ph[3], f2,f3);
            }
        }

        __syncthreads();
        if (i + 2 < T) issue_kv(i & 1, (i + 2) * 64);
    }

    l0 += __shfl_xor_sync(0xFFFFFFFFu, l0, 1);
    l0 += __shfl_xor_sync(0xFFFFFFFFu, l0, 2);
    l1 += __shfl_xor_sync(0xFFFFFFFFu, l1, 1);
    l1 += __shfl_xor_sync(0xFFFFFFFFu, l1, 2);
    float rl0 = 1.0f / l0, rl1 = 1.0f / l1;

    // write O (fp16 hi only) in [token][CH]
    int b = bh >> 4, h = bh & 15;
    int r0 = qb + warp * 16 + (lane >> 2);
    size_t base0 = ((size_t)(b * SEQ + r0)) * CH + h * DH + (lane & 3) * 2;
    size_t base1 = base0 + 8 * CH;
    #pragma unroll
    for (int nt = 0; nt < 8; nt++) {
        *(uint32_t*)(aoh + base0 + nt * 8) = pack_h2(oacc[nt][0] * rl0, oacc[nt][1] * rl0);
        *(uint32_t*)(aoh + base1 + nt * 8) = pack_h2(oacc[nt][2] * rl1, oacc[nt][3] * rl1);
    }
}

// ---------------------------------------------------------------------------
// Launch
// ---------------------------------------------------------------------------
extern "C" void kernel_launch(void* const* d_in, const int* in_sizes, int n_in,
                              void* d_out, int out_size)
{
    const float* x  = (const float*)d_in[0];
    const float* Wq = (const float*)d_in[1];
    const float* Wk = (const float*)d_in[2];
    const float* Wv = (const float*)d_in[3];
    const float* Wp = (const float*)d_in[4];
    const float* bp = (const float*)d_in[5];
    float* out = (float*)d_out;

    uint16_t *p_yh, *p_wh, *p_wl;
    uint16_t *p_qh, *p_kh, *p_kl, *p_vh, *p_vl, *p_aoh;
    cudaGetSymbolAddress((void**)&p_yh, g_yh);
    cudaGetSymbolAddress((void**)&p_wh, g_wh);
    cudaGetSymbolAddress((void**)&p_wl, g_wl);
    cudaGetSymbolAddress((void**)&p_qh, g_qh);
    cudaGetSymbolAddress((void**)&p_kh, g_kh);
    cudaGetSymbolAddress((void**)&p_kl, g_kl);
    cudaGetSymbolAddress((void**)&p_vh, g_vh);
    cudaGetSymbolAddress((void**)&p_vl, g_vl);
    cudaGetSymbolAddress((void**)&p_aoh, g_aoh);

    const int GEMM_SMEM = 128 * EPAD * 4;                  // 67584 (>= 2*3*PLANE*2)
    const int ATT_SMEM  = (128 * SSTR + 2 * KV_B) * 2;     // 92160 B
    static int configured = 0;
    if (!configured) {
        cudaFuncSetAttribute(gemm_async<true>,
                             cudaFuncAttributeMaxDynamicSharedMemorySize, GEMM_SMEM);
        cudaFuncSetAttribute(gemm_async<false>,
                             cudaFuncAttributeMaxDynamicSharedMemorySize, GEMM_SMEM);
        cudaFuncSetAttribute(attn_tc,
                             cudaFuncAttributeMaxDynamicSharedMemorySize, ATT_SMEM);
        configured = 1;
    }

    // 1. Pre-LN + weight split (x64, fp16) in one merged launch
    prep_split<<<TOKENS + 4 * CH * CH / 1024, 256>>>(x, Wq, Wk, Wv, Wp,
                                                     p_yh, p_wh, p_wl);

    // 2. QKV projections with fused head-LN + fp16 split epilogue
    dim3 gqkv(CH / 128, TOKENS / 128, 3);
    gemm_async<true><<<gqkv, 256, GEMM_SMEM>>>(p_yh, p_wh, p_wl,
                                               nullptr, nullptr,
                                               p_qh, p_kh, p_kl, p_vh, p_vl);

    // 3. fp16 tensor-core flash attention
    attn_tc<<<dim3(BATCH * HEADS, SEQ / 128), 256, ATT_SMEM>>>(p_qh, p_kh, p_kl,
                                                               p_vh, p_vl, p_aoh);

    // 4. Output projection + bias
    dim3 gout(CH / 128, TOKENS / 128, 1);
    gemm_async<false><<<gout, 256, GEMM_SMEM>>>(p_aoh,
                                                p_wh + (size_t)3 * CH * CH,
                                                p_wl + (size_t)3 * CH * CH,
                                                bp, out,
                                                nullptr, nullptr, nullptr, nullptr, nullptr);
}

// round 16
// speedup vs baseline: 1.3755x; 1.0016x over previous
#include <cuda_runtime.h>
#include <cuda_fp16.h>
#include <math.h>
#include <stdint.h>

// Problem constants
#define BATCH   16
#define SEQ     1024
#define CH      1024
#define HEADS   16
#define DH      64
#define TOKENS  (BATCH*SEQ)      // 16384
#define LN_EPS  1e-6f
#define QSCALE  0.125f           // Dh^-0.5
#define WSCALE  64.0f            // weight pre-scale (keeps w_lo fp16-normal)
#define WINV    (1.0f/64.0f)

// Scratch (device globals: allocation-free per harness rules)
__device__ uint16_t g_yh[TOKENS*CH];                          // y hi only
__device__ uint16_t g_wh[4*CH*CH];   __device__ uint16_t g_wl[4*CH*CH];
// per-head planes [B,H,N,DH]
__device__ uint16_t g_qh[TOKENS*CH];                          // q hi only
__device__ uint16_t g_kh[TOKENS*CH]; __device__ uint16_t g_kl[TOKENS*CH];
__device__ uint16_t g_vh[TOKENS*CH]; __device__ uint16_t g_vl[TOKENS*CH];
// attention output (hi only) in [token][CH] layout
__device__ uint16_t g_aoh[TOKENS*CH];

// ---------------------------------------------------------------------------
// helpers
// ---------------------------------------------------------------------------
__device__ __forceinline__ uint32_t smem_u32(const void* p) {
    return (uint32_t)__cvta_generic_to_shared(p);
}
__device__ __forceinline__ void ldsm_x4(uint32_t& r0, uint32_t& r1,
                                        uint32_t& r2, uint32_t& r3, uint32_t addr) {
    asm volatile("ldmatrix.sync.aligned.m8n8.x4.shared.b16 {%0,%1,%2,%3},[%4];"
                 : "=r"(r0), "=r"(r1), "=r"(r2), "=r"(r3) : "r"(addr));
}
__device__ __forceinline__ void ldsm_x4_t(uint32_t& r0, uint32_t& r1,
                                          uint32_t& r2, uint32_t& r3, uint32_t addr) {
    asm volatile("ldmatrix.sync.aligned.m8n8.x4.trans.shared.b16 {%0,%1,%2,%3},[%4];"
                 : "=r"(r0), "=r"(r1), "=r"(r2), "=r"(r3) : "r"(addr));
}
__device__ __forceinline__ void mma_f16(float* c,
                                        uint32_t a0, uint32_t a1, uint32_t a2, uint32_t a3,
                                        uint32_t b0, uint32_t b1) {
    asm volatile("mma.sync.aligned.m16n8k16.row.col.f32.f16.f16.f32 "
                 "{%0,%1,%2,%3},{%4,%5,%6,%7},{%8,%9},{%0,%1,%2,%3};"
                 : "+f"(c[0]), "+f"(c[1]), "+f"(c[2]), "+f"(c[3])
                 : "r"(a0), "r"(a1), "r"(a2), "r"(a3), "r"(b0), "r"(b1));
}
__device__ __forceinline__ uint32_t pack_h2(float a, float b) {
    __half2 h = __floats2half2_rn(a, b);
    return *(uint32_t*)&h;
}
__device__ __forceinline__ void split2h(float a, float b, uint32_t& hi, uint32_t& lo) {
    __half2 h = __floats2half2_rn(a, b);
    float ra = a - __half2float(__low2half(h));
    float rb = b - __half2float(__high2half(h));
    hi = *(uint32_t*)&h;
    lo = pack_h2(ra, rb);
}

#define CP16(dst, src) asm volatile("cp.async.cg.shared.global [%0],[%1],16;" :: "r"(dst), "l"(src))
#define CPCOMMIT()     asm volatile("cp.async.commit_group;")
#define CPWAIT1()      asm volatile("cp.async.wait_group 1;")
#define CPWAIT0()      asm volatile("cp.async.wait_group 0;")

// ---------------------------------------------------------------------------
// Kernel 1 (merged): blocks [0, TOKENS) do LayerNorm on x rows -> yh (fp16 hi).
// blocks [TOKENS, TOKENS+4096) split the 4 weight matrices x64 -> wh+wl.
// ---------------------------------------------------------------------------
__global__ __launch_bounds__(256) void prep_split(const float* __restrict__ x,
                                                  const float* __restrict__ W0,
                                                  const float* __restrict__ W1,
                                                  const float* __restrict__ W2,
                                                  const float* __restrict__ W3,
                                                  uint16_t* __restrict__ yh,
                                                  uint16_t* __restrict__ wh,
                                                  uint16_t* __restrict__ wl)
{
    int t = threadIdx.x;
    if (blockIdx.x < TOKENS) {
        int row = blockIdx.x;
        const float4* xr = (const float4*)(x + (size_t)row * CH);

        float4 v = xr[t];
        float s  = v.x + v.y + v.z + v.w;
        float ss = v.x*v.x + v.y*v.y + v.z*v.z + v.w*v.w;

        #pragma unroll
        for (int o = 16; o; o >>= 1) {
            s  += __shfl_xor_sync(0xFFFFFFFFu, s,  o);
            ss += __shfl_xor_sync(0xFFFFFFFFu, ss, o);
        }
        __shared__ float sh[16];
        int w = t >> 5, l = t & 31;
        if (l == 0) { sh[w] = s; sh[8 + w] = ss; }
        __syncthreads();
        float S = 0.f, SS = 0.f;
        #pragma unroll
        for (int i = 0; i < 8; i++) { S += sh[i]; SS += sh[8 + i]; }

        float mean = S * (1.0f / CH);
        float var  = SS * (1.0f / CH) - mean * mean;
        float inv  = rsqrtf(var + LN_EPS);

        uint32_t h01 = pack_h2((v.x - mean) * inv, (v.y - mean) * inv);
        uint32_t h23 = pack_h2((v.z - mean) * inv, (v.w - mean) * inv);
        *(uint2*)(yh + (size_t)row * CH + t * 4) = make_uint2(h01, h23);
    } else {
        int wid = blockIdx.x - TOKENS;        // 0..4095
        int z   = wid >> 10;
        int blk = wid & 1023;
        const float* W = (z == 0) ? W0 : (z == 1) ? W1 : (z == 2) ? W2 : W3;
        size_t base = (size_t)z * CH * CH;
        size_t off  = ((size_t)blk * 256 + t) * 4;

        float4 f = *(const float4*)(W + off);
        uint32_t h01, h23, l01, l23;
        split2h(f.x * WSCALE, f.y * WSCALE, h01, l01);
        split2h(f.z * WSCALE, f.w * WSCALE, h23, l23);
        *(uint2*)(wh + base + off) = make_uint2(h01, h23);
        *(uint2*)(wl + base + off) = make_uint2(l01, l23);
    }
}

// ---------------------------------------------------------------------------
// Kernel 2: fp16 tensor-core GEMM (NT), cp.async 3-stage single-sync pipeline.
// A hi-only, B hi+lo (weights x64). 2-pass: a*bh + a*bl.
// 128x128x32, warp tile 64x32, __launch_bounds__(256,2) (3x30KB x2 = 184KB ok).
// Per iter: wait_group -> syncthreads -> issue (i+2) into stage (i-1)%3 ->
// compute stage i%3. The top sync proves all warps finished stage (i-1),
// making the immediate refill safe: ONE sync per k-tile.
// QKV3 epilogue (smem-staged, thread-per-(row,head)):
//   z=0: head-LN * QSCALE -> qh only; z=1: head-LN -> kh+kl;
//   z=2: passthrough /64 -> vh+vl.  !QKV3: out = C/64 + bias (fp32).
// ---------------------------------------------------------------------------
#define BK    32
#define PADK  40
#define PLANE (128*PADK)   // fp16 elements per smem plane
#define STAGE (3*PLANE)    // fp16 elements per stage (A, Bh, Bl)
#define EPAD  132          // epilogue staging row stride (floats, mult of 4)

template<bool QKV3>
__global__ __launch_bounds__(256, 2) void gemm_async(const uint16_t* __restrict__ Ah,
                                                     const uint16_t* __restrict__ Bh_,
                                                     const uint16_t* __restrict__ Bl_,
                                                     const float* __restrict__ bias,
                                                     float* __restrict__ C,
                                                     uint16_t* __restrict__ pqh,
                                                     uint16_t* __restrict__ pkh,
                                                     uint16_t* __restrict__ pkl,
                                                     uint16_t* __restrict__ pvh,
                                                     uint16_t* __restrict__ pvl)
{
    extern __shared__ __align__(16) uint16_t smg[];

    int z = QKV3 ? blockIdx.z : 3;
    const uint16_t* Bh = Bh_;
    const uint16_t* Bl = Bl_;
    if (QKV3) {
        size_t zo = (size_t)z * CH * CH;
        Bh += zo; Bl += zo;
    }

    int t    = threadIdx.x;
    int lane = t & 31;
    int warp = t >> 5;
    int wm64 = (warp >> 2) * 64;
    int wn32 = (warp & 3) * 32;
    int bm = blockIdx.y * 128;
    int bn = blockIdx.x * 128;

    const uint16_t* Agh = Ah + (size_t)bm * CH;
    const uint16_t* Bgh = Bh + (size_t)bn * CH;
    const uint16_t* Bgl = Bl + (size_t)bn * CH;

    uint32_t smem_base = smem_u32(smg);

    float acc[4][4][4];
    #pragma unroll
    for (int i = 0; i < 4; i++)
        #pragma unroll
        for (int j = 0; j < 4; j++)
            #pragma unroll
            for (int c = 0; c < 4; c++) acc[i][j][c] = 0.f;

    // per-thread cp.async chunks: 2 per plane (512 chunks of 16B per plane)
    int c0r = t >> 2,          c0c = (t & 3) * 8;
    int c1r = (t + 256) >> 2,  c1c = ((t + 256) & 3) * 8;

    auto issue = [&](int stage, int k0) {
        uint32_t sb = smem_base + stage * (STAGE * 2);
        uint32_t s0 = sb + (c0r * PADK + c0c) * 2;
        uint32_t s1 = sb + (c1r * PADK + c1c) * 2;
        CP16(s0 + 0*PLANE*2, Agh + (size_t)c0r * CH + k0 + c0c);
        CP16(s1 + 0*PLANE*2, Agh + (size_t)c1r * CH + k0 + c1c);
        CP16(s0 + 1*PLANE*2, Bgh + (size_t)c0r * CH + k0 + c0c);
        CP16(s1 + 1*PLANE*2, Bgh + (size_t)c1r * CH + k0 + c1c);
        CP16(s0 + 2*PLANE*2, Bgl + (size_t)c0r * CH + k0 + c0c);
        CP16(s1 + 2*PLANE*2, Bgl + (size_t)c1r * CH + k0 + c1c);
        CPCOMMIT();
    };

    int a_r    = lane & 15;
    int a_koff = (lane >> 4) << 3;
    int b_n    = (lane & 7) + ((lane >> 4) << 3);
    int b_koff = ((lane >> 3) & 1) << 3;

    const int T = CH / BK;   // 32
    issue(0, 0);
    issue(1, BK);

    for (int i = 0; i < T; i++) {
        if (i + 1 < T) { CPWAIT1(); } else { CPWAIT0(); }
        __syncthreads();
        // refill the stage consumed in iteration i-1 (safe: sync above)
        if (i + 2 < T) issue((i + 2) % 3, (i + 2) * BK);

        uint16_t* sA  = smg + (i % 3) * STAGE;
        uint16_t* sBh = sA + PLANE;
        uint16_t* sBl = sBh + PLANE;

        #pragma unroll
        for (int kc = 0; kc < 2; kc++) {
            int ko = kc * 16;
            uint32_t a[4][4], bh[4][2], bl[4][2];
            #pragma unroll
            for (int mt = 0; mt < 4; mt++) {
                int off = (wm64 + mt * 16 + a_r) * PADK + ko + a_koff;
                ldsm_x4(a[mt][0], a[mt][1], a[mt][2], a[mt][3], smem_u32(&sA[off]));
            }
            #pragma unroll
            for (int p = 0; p < 2; p++) {
                int off = (wn32 + p * 16 + b_n) * PADK + ko + b_koff;
                uint32_t r0, r1, r2, r3;
                ldsm_x4(r0, r1, r2, r3, smem_u32(&sBh[off]));
                bh[2*p][0] = r0; bh[2*p][1] = r1; bh[2*p+1][0] = r2; bh[2*p+1][1] = r3;
                ldsm_x4(r0, r1, r2, r3, smem_u32(&sBl[off]));
                bl[2*p][0] = r0; bl[2*p][1] = r1; bl[2*p+1][0] = r2; bl[2*p+1][1] = r3;
            }
            #pragma unroll
            for (int mt = 0; mt < 4; mt++)
                #pragma unroll
                for (int nt = 0; nt < 4; nt++) {
                    float* c = acc[mt][nt];
                    mma_f16(c, a[mt][0], a[mt][1], a[mt][2], a[mt][3],
                            bh[nt][0], bh[nt][1]);
                    mma_f16(c, a[mt][0], a[mt][1], a[mt][2], a[mt][3],
                            bl[nt][0], bl[nt][1]);
                }
        }
    }
    __syncthreads();   // mainloop smem quiesced before epilogue staging

    int lane4 = lane >> 2;
    int lpair = (lane & 3) * 2;

    if (QKV3) {
        // ---- stage fp32 tile to smem ----
        float* st = (float*)smg;
        #pragma unroll
        for (int mt = 0; mt < 4; mt++) {
            int r0 = wm64 + mt * 16 + lane4;
            #pragma unroll
            for (int nt = 0; nt < 4; nt++) {
                int col = wn32 + nt * 8 + lpair;
                float* c = acc[mt][nt];
                *(float2*)&st[(size_t)r0 * EPAD + col]       = make_float2(c[0], c[1]);
                *(float2*)&st[(size_t)(r0 + 8) * EPAD + col] = make_float2(c[2], c[3]);
            }
        }
        __syncthreads();

        // ---- thread-per-(row, head): LN / descale + fp16 write ----
        int r   = t >> 1;
        int hh  = t & 1;
        const float* v = st + (size_t)r * EPAD + hh * 64;

        float mean = 0.f, inv = WINV;       // z==2: passthrough with /64
        if (z < 2) {
            float s = 0.f, ss = 0.f;
            #pragma unroll
            for (int j = 0; j < 16; j++) {
                float4 f = *(const float4*)(v + j * 4);
                s  += (f.x + f.y) + (f.z + f.w);
                ss += (f.x*f.x + f.y*f.y) + (f.z*f.z + f.w*f.w);
            }
            mean = s * (1.0f / DH);
            float var = ss * (1.0f / DH) - mean * mean;
            inv = rsqrtf(var + LN_EPS) * (z == 0 ? QSCALE : 1.0f);
        }

        int row = bm + r;
        int bb  = row >> 10, n = row & 1023;
        int h   = blockIdx.x * 2 + hh;
        size_t base = (((size_t)(bb * HEADS + h)) * SEQ + n) * DH;

        if (z == 0) {
            #pragma unroll
            for (int j = 0; j < 16; j++) {
                float4 f = *(const float4*)(v + j * 4);
                uint32_t h01 = pack_h2((f.x - mean) * inv, (f.y - mean) * inv);
                uint32_t h23 = pack_h2((f.z - mean) * inv, (f.w - mean) * inv);
                *(uint2*)(pqh + base + j * 4) = make_uint2(h01, h23);
            }
        } else {
            uint16_t* dh = (z == 1) ? pkh : pvh;
            uint16_t* dl = (z == 1) ? pkl : pvl;
            #pragma unroll
            for (int j = 0; j < 16; j++) {
                float4 f = *(const float4*)(v + j * 4);
                uint32_t h01, h23, l01, l23;
                split2h((f.x - mean) * inv, (f.y - mean) * inv, h01, l01);
                split2h((f.z - mean) * inv, (f.w - mean) * inv, h23, l23);
                *(uint2*)(dh + base + j * 4) = make_uint2(h01, h23);
                *(uint2*)(dl + base + j * 4) = make_uint2(l01, l23);
            }
        }
    } else {
        // out-projection: C/64 + bias, fp32
        #pragma unroll
        for (int mt = 0; mt < 4; mt++) {
            int row = bm + wm64 + mt * 16 + lane4;
            #pragma unroll
            for (int nt = 0; nt < 4; nt++) {
                int col = bn + wn32 + nt * 8 + lpair;
                float b0 = bias[col], b1 = bias[col + 1];
                float* c = acc[mt][nt];
                *(float2*)(C + (size_t)row * CH + col) =
                    make_float2(c[0] * WINV + b0, c[1] * WINV + b1);
                *(float2*)(C + (size_t)(row + 8) * CH + col) =
                    make_float2(c[2] * WINV + b0, c[3] * WINV + b1);
            }
        }
    }
}

// ---------------------------------------------------------------------------
// Kernel 3: fp16 tensor-core flash attention (no max tracking: |s|<=8).
// Q hi-only resident; QK: q*(kh+kl) 2-pass; PV: p*(vh+vl) 2-pass (p hi-only).
// KV double-buffered cp.async; __launch_bounds__(256,2).
// ---------------------------------------------------------------------------
#define SSTR    72
#define KV_B    (4*64*SSTR)        // fp16 elements per KV stage (kh,kl,vh,vl)

__global__ __launch_bounds__(256, 2) void attn_tc(const uint16_t* __restrict__ qh,
                                                  const uint16_t* __restrict__ kh,
                                                  const uint16_t* __restrict__ kl,
                                                  const uint16_t* __restrict__ vh,
                                                  const uint16_t* __restrict__ vl,
                                                  uint16_t* __restrict__ aoh)
{
    extern __shared__ __align__(16) uint16_t sm[];
    uint16_t* Qh = sm;                       // 128*SSTR
    uint16_t* KV = Qh + 128 * SSTR;          // 2 stages of KV_B

    int bh = blockIdx.x;
    int qb = blockIdx.y * 128;
    int t = threadIdx.x, lane = t & 31, warp = t >> 5;
    size_t plane = (size_t)bh * SEQ * DH;

    int k0r = t >> 3,         k0c = (t & 7) * 8;
    int k1r = (t + 256) >> 3, k1c = ((t + 256) & 7) * 8;
    uint32_t kv_base = smem_u32(KV);

    auto issue_kv = [&](int stage, int kt) {
        uint32_t sb = kv_base + stage * (KV_B * 2);
        uint32_t s0 = sb + (k0r * SSTR + k0c) * 2;
        uint32_t s1 = sb + (k1r * SSTR + k1c) * 2;
        size_t g0 = plane + (size_t)(kt + k0r) * DH + k0c;
        size_t g1 = plane + (size_t)(kt + k1r) * DH + k1c;
        const int PL = 64 * SSTR * 2;
        CP16(s0 + 0*PL, kh + g0);  CP16(s1 + 0*PL, kh + g1);
        CP16(s0 + 1*PL, kl + g0);  CP16(s1 + 1*PL, kl + g1);
        CP16(s0 + 2*PL, vh + g0);  CP16(s1 + 2*PL, vh + g1);
        CP16(s0 + 3*PL, vl + g0);  CP16(s1 + 3*PL, vl + g1);
        CPCOMMIT();
    };

    issue_kv(0, 0);
    issue_kv(1, 64);

    // Load Q tile (hi only): 1024 x 16B chunks, 4 per thread
    #pragma unroll
    for (int i = 0; i < 4; i++) {
        int f = t + i * 256;
        int row = f >> 3, c = (f & 7) * 8;
        *(uint4*)&Qh[row * SSTR + c] =
            *(const uint4*)(qh + plane + (size_t)(qb + row) * DH + c);
    }
    __syncthreads();

    int a_r = lane & 15, a_ko = (lane >> 4) << 3;

    float oacc[8][4];
    #pragma unroll
    for (int i = 0; i < 8; i++)
        #pragma unroll
        for (int j = 0; j < 4; j++) oacc[i][j] = 0.f;
    float l0 = 0.f, l1 = 0.f;

    int b_n  = (lane & 7) + ((lane >> 4) << 3);
    int b_ko = ((lane >> 3) & 1) << 3;
    int v_r  = lane & 15;
    int v_co = (lane >> 4) * 8;

    const int T = SEQ / 64;
    for (int i = 0; i < T; i++) {
        if (i + 1 < T) { CPWAIT1(); } else { CPWAIT0(); }
        __syncthreads();

        uint16_t* Kh = KV + (i & 1) * KV_B;
        uint16_t* Kl = Kh + 64 * SSTR;
        uint16_t* Vh = Kl + 64 * SSTR;
        uint16_t* Vl = Vh + 64 * SSTR;

        float sacc[8][4];
        #pragma unroll
        for (int a = 0; a < 8; a++)
            #pragma unroll
            for (int c = 0; c < 4; c++) sacc[a][c] = 0.f;

        // ----- S = Q K^T (2-pass: q*kh + q*kl), ch-outer -----
        #pragma unroll
        for (int ch = 0; ch < 4; ch++) {
            uint32_t q0,q1,q2,q3;
            int qoff = (warp * 16 + a_r) * SSTR + ch * 16 + a_ko;
            ldsm_x4(q0,q1,q2,q3, smem_u32(&Qh[qoff]));
            #pragma unroll
            for (int kp = 0; kp < 4; kp++) {
                int off = (kp * 16 + b_n) * SSTR + ch * 16 + b_ko;
                uint32_t h0,h1,h2,h3, f0,f1,f2,f3;
                ldsm_x4(h0,h1,h2,h3, smem_u32(&Kh[off]));
                ldsm_x4(f0,f1,f2,f3, smem_u32(&Kl[off]));
                float* c0 = sacc[2*kp];
                float* c1 = sacc[2*kp+1];
                mma_f16(c0, q0,q1,q2,q3, h0,h1);
                mma_f16(c1, q0,q1,q2,q3, h2,h3);
                mma_f16(c0, q0,q1,q2,q3, f0,f1);
                mma_f16(c1, q0,q1,q2,q3, f2,f3);
            }
        }

        // ----- exp + l accumulation -----
        #pragma unroll
        for (int nt = 0; nt < 8; nt++) {
            float p0 = __expf(sacc[nt][0]);
            float p1 = __expf(sacc[nt][1]);
            float p2 = __expf(sacc[nt][2]);
            float p3 = __expf(sacc[nt][3]);
            sacc[nt][0] = p0; sacc[nt][1] = p1;
            sacc[nt][2] = p2; sacc[nt][3] = p3;
            l0 += p0 + p1;
            l1 += p2 + p3;
        }

        // ----- O += P V (2-pass: p*vh + p*vl, p hi-only) -----
        #pragma unroll
        for (int j = 0; j < 4; j++) {
            float* ca = sacc[2*j];
            float* cb = sacc[2*j+1];
            uint32_t ph[4];
            ph[0] = pack_h2(ca[0], ca[1]);
            ph[1] = pack_h2(ca[2], ca[3]);
            ph[2] = pack_h2(cb[0], cb[1]);
            ph[3] = pack_h2(cb[2], cb[3]);
            #pragma unroll
            for (int dp = 0; dp < 4; dp++) {
                int off = (j * 16 + v_r) * SSTR + dp * 16 + v_co;
                uint32_t b0,b1,b2,b3, f0,f1,f2,f3;
                ldsm_x4_t(b0,b1,b2,b3, smem_u32(&Vh[off]));
                ldsm_x4_t(f0,f1,f2,f3, smem_u32(&Vl[off]));
                float* o0 = oacc[2*dp];
                float* o1 = oacc[2*dp+1];
                mma_f16(o0, ph[0],ph[1],ph[2],ph[3], b0,b1);
                mma_f16(o1, ph[0],ph[1],ph[2],ph[3], b2,b3);
                mma_f16(o0, ph[0],ph[1],ph[2],ph[3], f0,f1);
                mma_f16(o1, ph[0],ph[1],ph[2],ph[3], f2,f3);
            }
        }

        __syncthreads();
        if (i + 2 < T) issue_kv(i & 1, (i + 2) * 64);
    }

    l0 += __shfl_xor_sync(0xFFFFFFFFu, l0, 1);
    l0 += __shfl_xor_sync(0xFFFFFFFFu, l0, 2);
    l1 += __shfl_xor_sync(0xFFFFFFFFu, l1, 1);
    l1 += __shfl_xor_sync(0xFFFFFFFFu, l1, 2);
    float rl0 = 1.0f / l0, rl1 = 1.0f / l1;

    // write O (fp16 hi only) in [token][CH]
    int b = bh >> 4, h = bh & 15;
    int r0 = qb + warp * 16 + (lane >> 2);
    size_t base0 = ((size_t)(b * SEQ + r0)) * CH + h * DH + (lane & 3) * 2;
    size_t base1 = base0 + 8 * CH;
    #pragma unroll
    for (int nt = 0; nt < 8; nt++) {
        *(uint32_t*)(aoh + base0 + nt * 8) = pack_h2(oacc[nt][0] * rl0, oacc[nt][1] * rl0);
        *(uint32_t*)(aoh + base1 + nt * 8) = pack_h2(oacc[nt][2] * rl1, oacc[nt][3] * rl1);
    }
}

// ---------------------------------------------------------------------------
// Launch
// ---------------------------------------------------------------------------
extern "C" void kernel_launch(void* const* d_in, const int* in_sizes, int n_in,
                              void* d_out, int out_size)
{
    const float* x  = (const float*)d_in[0];
    const float* Wq = (const float*)d_in[1];
    const float* Wk = (const float*)d_in[2];
    const float* Wv = (const float*)d_in[3];
    const float* Wp = (const float*)d_in[4];
    const float* bp = (const float*)d_in[5];
    float* out = (float*)d_out;

    uint16_t *p_yh, *p_wh, *p_wl;
    uint16_t *p_qh, *p_kh, *p_kl, *p_vh, *p_vl, *p_aoh;
    cudaGetSymbolAddress((void**)&p_yh, g_yh);
    cudaGetSymbolAddress((void**)&p_wh, g_wh);
    cudaGetSymbolAddress((void**)&p_wl, g_wl);
    cudaGetSymbolAddress((void**)&p_qh, g_qh);
    cudaGetSymbolAddress((void**)&p_kh, g_kh);
    cudaGetSymbolAddress((void**)&p_kl, g_kl);
    cudaGetSymbolAddress((void**)&p_vh, g_vh);
    cudaGetSymbolAddress((void**)&p_vl, g_vl);
    cudaGetSymbolAddress((void**)&p_aoh, g_aoh);

    const int GEMM_SMEM = 3 * STAGE * 2;                   // 92160 B (>= EPAD staging)
    const int ATT_SMEM  = (128 * SSTR + 2 * KV_B) * 2;     // 92160 B
    static int configured = 0;
    if (!configured) {
        cudaFuncSetAttribute(gemm_async<true>,
                             cudaFuncAttributeMaxDynamicSharedMemorySize, GEMM_SMEM);
        cudaFuncSetAttribute(gemm_async<false>,
                             cudaFuncAttributeMaxDynamicSharedMemorySize, GEMM_SMEM);
        cudaFuncSetAttribute(attn_tc,
                             cudaFuncAttributeMaxDynamicSharedMemorySize, ATT_SMEM);
        configured = 1;
    }

    // 1. Pre-LN + weight split (x64, fp16) in one merged launch
    prep_split<<<TOKENS + 4 * CH * CH / 1024, 256>>>(x, Wq, Wk, Wv, Wp,
                                                     p_yh, p_wh, p_wl);

    // 2. QKV projections with fused head-LN + fp16 split epilogue
    dim3 gqkv(CH / 128, TOKENS / 128, 3);
    gemm_async<true><<<gqkv, 256, GEMM_SMEM>>>(p_yh, p_wh, p_wl,
                                               nullptr, nullptr,
                                               p_qh, p_kh, p_kl, p_vh, p_vl);

    // 3. fp16 tensor-core flash attention
    attn_tc<<<dim3(BATCH * HEADS, SEQ / 128), 256, ATT_SMEM>>>(p_qh, p_kh, p_kl,
                                                               p_vh, p_vl, p_aoh);

    // 4. Output projection + bias
    dim3 gout(CH / 128, TOKENS / 128, 1);
    gemm_async<false><<<gout, 256, GEMM_SMEM>>>(p_aoh,
                                                p_wh + (size_t)3 * CH * CH,
                                                p_wl + (size_t)3 * CH * CH,
                                                bp, out,
                                                nullptr, nullptr, nullptr, nullptr, nullptr);
}